// round 1
// baseline (speedup 1.0000x reference)
#include <cuda_runtime.h>

// Problem constants
constexpr int B_  = 4;
constexpr int S_  = 2048;
constexpr int C_  = 1024;
constexpr int H_  = 16;
constexpr int HS_ = 64;
constexpr int M_  = B_ * S_;                    // 8192 rows
constexpr int QKV_ELEMS = B_ * H_ * S_ * HS_;   // 8388608

// Scratch (device globals: allocation inside kernel_launch is forbidden)
__device__ float g_q[QKV_ELEMS];
__device__ float g_k[QKV_ELEMS];
__device__ float g_v[QKV_ELEMS];
__device__ float g_o[QKV_ELEMS];       // attention output, [B,H,S,HS]
__device__ float g_WpT[C_ * C_];       // Wp transposed: WpT[c][n] = Wp[n][c]

// ---------------------------------------------------------------------------
// Wp transpose so the projection GEMM streams B coalesced.
// ---------------------------------------------------------------------------
__global__ void transpose_wp_kernel(const float* __restrict__ Wp) {
    int idx = blockIdx.x * 256 + threadIdx.x;   // 0 .. C*C-1
    int n = idx / C_;
    int c = idx - n * C_;
    g_WpT[c * C_ + n] = Wp[n * C_ + c];
}

// ---------------------------------------------------------------------------
// QKV projection: out[b,h,s,d] = sum_c x[b,s,c] * W[h,c,d]
// One 64-wide N tile == one head (HS==64), so the weight tile is a contiguous
// [16 x 64] slab per K-step. 64x64x16 tiling, 4x4 per thread, 256 threads.
// blockIdx.z in {0,1,2} selects Q/K/V.
// ---------------------------------------------------------------------------
__global__ __launch_bounds__(256) void qkv_kernel(
    const float* __restrict__ x,
    const float* __restrict__ Wq,
    const float* __restrict__ Wk,
    const float* __restrict__ Wv)
{
    const float* W   = (blockIdx.z == 0) ? Wq : (blockIdx.z == 1) ? Wk : Wv;
    float*       out = (blockIdx.z == 0) ? g_q : (blockIdx.z == 1) ? g_k : g_v;

    const int h  = blockIdx.x;           // head index == n-tile
    const int m0 = blockIdx.y * 64;

    __shared__ float As[16][64];         // [k][m]
    __shared__ float Bs[16][64];         // [k][d]

    const int tid  = threadIdx.x;
    const int trow = tid >> 4;           // 0..15 -> 4 output rows
    const int tcol = tid & 15;           // 0..15 -> 4 output cols

    const int lrow = tid >> 2;           // A load: row 0..63
    const int lk4  = tid & 3;            // A load: which float4 of the 16-wide K slab
    const int lkk  = tid >> 4;           // B load: k 0..15
    const int ld4  = tid & 15;           // B load: float4 within 64

    const float* Wh = W + (size_t)h * C_ * HS_;
    const float* Arow = x + (size_t)(m0 + lrow) * C_;

    float acc[4][4];
    #pragma unroll
    for (int i = 0; i < 4; i++)
        #pragma unroll
        for (int j = 0; j < 4; j++) acc[i][j] = 0.f;

    for (int k0 = 0; k0 < C_; k0 += 16) {
        float4 av = *(const float4*)(Arow + k0 + lk4 * 4);
        As[lk4 * 4 + 0][lrow] = av.x;
        As[lk4 * 4 + 1][lrow] = av.y;
        As[lk4 * 4 + 2][lrow] = av.z;
        As[lk4 * 4 + 3][lrow] = av.w;
        *(float4*)&Bs[lkk][ld4 * 4] =
            *(const float4*)(Wh + (size_t)(k0 + lkk) * HS_ + ld4 * 4);
        __syncthreads();

        #pragma unroll
        for (int k = 0; k < 16; k++) {
            float4 a4 = ((const float4*)&As[k][0])[trow];
            float4 b4 = ((const float4*)&Bs[k][0])[tcol];
            float a[4] = {a4.x, a4.y, a4.z, a4.w};
            float b[4] = {b4.x, b4.y, b4.z, b4.w};
            #pragma unroll
            for (int i = 0; i < 4; i++)
                #pragma unroll
                for (int j = 0; j < 4; j++) acc[i][j] += a[i] * b[j];
        }
        __syncthreads();
    }

    // out[((b*H+h)*S + s)*HS + d]
    #pragma unroll
    for (int i = 0; i < 4; i++) {
        int m = m0 + trow * 4 + i;
        int b = m / S_;
        int s = m - b * S_;
        float4 v = make_float4(acc[i][0], acc[i][1], acc[i][2], acc[i][3]);
        *(float4*)(out + ((size_t)(b * H_ + h) * S_ + s) * HS_ + tcol * 4) = v;
    }
}

// ---------------------------------------------------------------------------
// Causal flash attention, fp32. One block per (query-tile of 64, h, b);
// one thread per query row: q[64] and o[64] live in registers, K/V tiles in
// smem. Online softmax with the "rescale only when the max moves" branch.
// q is pre-scaled by 1/sqrt(HS) = 0.125.
// ---------------------------------------------------------------------------
__global__ __launch_bounds__(64) void attn_kernel() {
    const int qb = blockIdx.x;
    const int h  = blockIdx.y;
    const int b  = blockIdx.z;
    const size_t base = (size_t)(b * H_ + h) * S_ * HS_;
    const float* Q = g_q + base;
    const float* K = g_k + base;
    const float* V = g_v + base;
    float*       O = g_o + base;

    const int tid = threadIdx.x;
    const int r   = qb * 64 + tid;      // this thread's query row

    float q[64];
    #pragma unroll
    for (int i = 0; i < 16; i++) {
        float4 t = ((const float4*)(Q + (size_t)r * HS_))[i];
        q[4*i+0] = t.x * 0.125f;
        q[4*i+1] = t.y * 0.125f;
        q[4*i+2] = t.z * 0.125f;
        q[4*i+3] = t.w * 0.125f;
    }

    float m = -1e30f, l = 0.f;
    float o[64];
    #pragma unroll
    for (int i = 0; i < 64; i++) o[i] = 0.f;

    __shared__ float Ks[64 * 64];
    __shared__ float Vs[64 * 64];

    for (int kt = 0; kt <= qb; kt++) {
        __syncthreads();
        const float4* Ksrc = (const float4*)(K + (size_t)kt * 64 * HS_);
        const float4* Vsrc = (const float4*)(V + (size_t)kt * 64 * HS_);
        #pragma unroll
        for (int i = 0; i < 16; i++) {   // fully coalesced 1KB/instr
            ((float4*)Ks)[tid + i * 64] = Ksrc[tid + i * 64];
            ((float4*)Vs)[tid + i * 64] = Vsrc[tid + i * 64];
        }
        __syncthreads();

        const int jmax = (kt == qb) ? (tid + 1) : 64;   // causal mask on diagonal tile
        for (int j = 0; j < jmax; j++) {
            const float4* k4 = (const float4*)(Ks + j * 64);
            float s0 = 0.f, s1 = 0.f, s2 = 0.f, s3 = 0.f;
            #pragma unroll
            for (int d4 = 0; d4 < 16; d4++) {
                float4 kv = k4[d4];
                s0 += q[4*d4+0] * kv.x;
                s1 += q[4*d4+1] * kv.y;
                s2 += q[4*d4+2] * kv.z;
                s3 += q[4*d4+3] * kv.w;
            }
            float s = (s0 + s1) + (s2 + s3);
            const float4* v4 = (const float4*)(Vs + j * 64);
            if (s <= m) {                         // common path: no rescale
                float p = __expf(s - m);
                l += p;
                #pragma unroll
                for (int d4 = 0; d4 < 16; d4++) {
                    float4 vv = v4[d4];
                    o[4*d4+0] += p * vv.x;
                    o[4*d4+1] += p * vv.y;
                    o[4*d4+2] += p * vv.z;
                    o[4*d4+3] += p * vv.w;
                }
            } else {                              // new max: rescale, p == 1
                float corr = __expf(m - s);
                m = s;
                l = l * corr + 1.f;
                #pragma unroll
                for (int d4 = 0; d4 < 16; d4++) {
                    float4 vv = v4[d4];
                    o[4*d4+0] = o[4*d4+0] * corr + vv.x;
                    o[4*d4+1] = o[4*d4+1] * corr + vv.y;
                    o[4*d4+2] = o[4*d4+2] * corr + vv.z;
                    o[4*d4+3] = o[4*d4+3] * corr + vv.w;
                }
            }
        }
    }

    float inv = 1.f / l;
    #pragma unroll
    for (int i = 0; i < 16; i++) {
        float4 t = make_float4(o[4*i+0] * inv, o[4*i+1] * inv,
                               o[4*i+2] * inv, o[4*i+3] * inv);
        ((float4*)(O + (size_t)r * HS_))[i] = t;
    }
}

// ---------------------------------------------------------------------------
// Output projection: out[m,n] = sum_k Ocat[m,k] * WpT[k,n] + bp[n]
// Ocat[m,k] gathers the head-concat layout from g_o in the A-load.
// ---------------------------------------------------------------------------
__global__ __launch_bounds__(256) void proj_kernel(
    const float* __restrict__ bp, float* __restrict__ out)
{
    const int n0 = blockIdx.x * 64;
    const int m0 = blockIdx.y * 64;

    __shared__ float As[16][64];
    __shared__ float Bs[16][64];

    const int tid  = threadIdx.x;
    const int trow = tid >> 4;
    const int tcol = tid & 15;
    const int lrow = tid >> 2;
    const int lk4  = tid & 3;
    const int lkk  = tid >> 4;
    const int ld4  = tid & 15;

    const int m  = m0 + lrow;
    const int bb = m / S_;
    const int ss = m - bb * S_;

    float acc[4][4];
    #pragma unroll
    for (int i = 0; i < 4; i++)
        #pragma unroll
        for (int j = 0; j < 4; j++) acc[i][j] = 0.f;

    for (int k0 = 0; k0 < C_; k0 += 16) {
        int kk   = k0 + lk4 * 4;
        int head = kk >> 6;           // k / HS
        int din  = kk & 63;           // k % HS (4-aligned -> float4 safe)
        float4 av = *(const float4*)(
            g_o + ((size_t)(bb * H_ + head) * S_ + ss) * HS_ + din);
        As[lk4 * 4 + 0][lrow] = av.x;
        As[lk4 * 4 + 1][lrow] = av.y;
        As[lk4 * 4 + 2][lrow] = av.z;
        As[lk4 * 4 + 3][lrow] = av.w;
        *(float4*)&Bs[lkk][ld4 * 4] =
            *(const float4*)(g_WpT + (size_t)(k0 + lkk) * C_ + n0 + ld4 * 4);
        __syncthreads();

        #pragma unroll
        for (int k = 0; k < 16; k++) {
            float4 a4 = ((const float4*)&As[k][0])[trow];
            float4 b4 = ((const float4*)&Bs[k][0])[tcol];
            float a[4] = {a4.x, a4.y, a4.z, a4.w};
            float bv[4] = {b4.x, b4.y, b4.z, b4.w};
            #pragma unroll
            for (int i = 0; i < 4; i++)
                #pragma unroll
                for (int j = 0; j < 4; j++) acc[i][j] += a[i] * bv[j];
        }
        __syncthreads();
    }

    float4 bias = *(const float4*)(bp + n0 + tcol * 4);
    #pragma unroll
    for (int i = 0; i < 4; i++) {
        int mm = m0 + trow * 4 + i;
        float4 v = make_float4(acc[i][0] + bias.x, acc[i][1] + bias.y,
                               acc[i][2] + bias.z, acc[i][3] + bias.w);
        *(float4*)(out + (size_t)mm * C_ + n0 + tcol * 4) = v;
    }
}

// ---------------------------------------------------------------------------
// Launch: transpose -> QKV GEMM -> flash attention -> projection.
// Default stream, graph-capturable (no sync, no alloc).
// ---------------------------------------------------------------------------
extern "C" void kernel_launch(void* const* d_in, const int* in_sizes, int n_in,
                              void* d_out, int out_size) {
    const float* x  = (const float*)d_in[0];
    const float* Wq = (const float*)d_in[1];
    const float* Wk = (const float*)d_in[2];
    const float* Wv = (const float*)d_in[3];
    const float* Wp = (const float*)d_in[4];
    const float* bp = (const float*)d_in[5];
    float* out = (float*)d_out;

    transpose_wp_kernel<<<(C_ * C_) / 256, 256>>>(Wp);
    qkv_kernel<<<dim3(H_, M_ / 64, 3), 256>>>(x, Wq, Wk, Wv);
    attn_kernel<<<dim3(S_ / 64, H_, B_), 64>>>();
    proj_kernel<<<dim3(C_ / 64, M_ / 64), 256>>>(bp, out);
}

// round 2
// speedup vs baseline: 1.2769x; 1.2769x over previous
#include <cuda_runtime.h>

constexpr int B_  = 4;
constexpr int S_  = 2048;
constexpr int C_  = 1024;
constexpr int H_  = 16;
constexpr int HS_ = 64;
constexpr int M_  = B_ * S_;                    // 8192
constexpr int QKV_ELEMS = B_ * H_ * S_ * HS_;   // 8388608

__device__ float g_q[QKV_ELEMS];
__device__ float g_k[QKV_ELEMS];
__device__ float g_v[QKV_ELEMS];
__device__ float g_o[QKV_ELEMS];       // attention output [B,H,S,HS]
__device__ float g_WpT[C_ * C_];       // WpT[c][n] = Wp[n][c]

// ---------------------------------------------------------------------------
__global__ void transpose_wp_kernel(const float* __restrict__ Wp) {
    int idx = blockIdx.x * 256 + threadIdx.x;
    int n = idx >> 10;
    int c = idx & 1023;
    g_WpT[c * C_ + n] = Wp[n * C_ + c];
}

// ---------------------------------------------------------------------------
// QKV GEMM: M=8192, N=1024 (16 heads x 64), 128x128x16 tiles, 8x8 per thread.
// blockIdx.z selects Q/K/V. Output written in [b,h,s,d] layout.
// ---------------------------------------------------------------------------
__global__ __launch_bounds__(256) void qkv_gemm(
    const float* __restrict__ x,
    const float* __restrict__ Wq,
    const float* __restrict__ Wk,
    const float* __restrict__ Wv)
{
    const float* W   = (blockIdx.z == 0) ? Wq : (blockIdx.z == 1) ? Wk : Wv;
    float*       out = (blockIdx.z == 0) ? g_q : (blockIdx.z == 1) ? g_k : g_v;

    const int n0 = blockIdx.x * 128;
    const int m0 = blockIdx.y * 128;

    __shared__ float As[16][128];   // [k][m]
    __shared__ float Bs[16][128];   // [k][n]

    const int tid = threadIdx.x;
    const int tx  = tid & 15;
    const int ty  = tid >> 4;

    float acc[8][8];
    #pragma unroll
    for (int i = 0; i < 8; i++)
        #pragma unroll
        for (int j = 0; j < 8; j++) acc[i][j] = 0.f;

    const int h0 = n0 >> 6;   // first of two heads covered by this N tile

    for (int k0 = 0; k0 < C_; k0 += 16) {
        // A: 128x16, transpose-on-store
        #pragma unroll
        for (int it = 0; it < 2; it++) {
            int ar  = it * 64 + (tid >> 2);
            int ac4 = tid & 3;
            float4 v = *(const float4*)(x + (size_t)(m0 + ar) * C_ + k0 + ac4 * 4);
            As[ac4 * 4 + 0][ar] = v.x;
            As[ac4 * 4 + 1][ar] = v.y;
            As[ac4 * 4 + 2][ar] = v.z;
            As[ac4 * 4 + 3][ar] = v.w;
        }
        // B: 16x128, gather across two heads
        #pragma unroll
        for (int it = 0; it < 2; it++) {
            int bk  = it * 8 + (tid >> 5);
            int bc4 = tid & 31;
            int n   = n0 + bc4 * 4;
            const float* src = W + (size_t)(n >> 6) * (C_ * HS_)
                                 + (size_t)(k0 + bk) * HS_ + (n & 63);
            *(float4*)&Bs[bk][bc4 * 4] = *(const float4*)src;
        }
        __syncthreads();

        #pragma unroll
        for (int k = 0; k < 16; k++) {
            float a[8], b[8];
            *(float4*)&a[0] = *(const float4*)&As[k][ty * 4];
            *(float4*)&a[4] = *(const float4*)&As[k][64 + ty * 4];
            *(float4*)&b[0] = *(const float4*)&Bs[k][tx * 4];
            *(float4*)&b[4] = *(const float4*)&Bs[k][64 + tx * 4];
            #pragma unroll
            for (int i = 0; i < 8; i++)
                #pragma unroll
                for (int j = 0; j < 8; j++) acc[i][j] += a[i] * b[j];
        }
        __syncthreads();
    }

    #pragma unroll
    for (int i = 0; i < 8; i++) {
        int m = m0 + ((i < 4) ? (ty * 4 + i) : (64 + ty * 4 + i - 4));
        int b = m >> 11;
        int s = m & 2047;
        float* r0 = out + ((size_t)(b * H_ + h0)     * S_ + s) * HS_ + tx * 4;
        float* r1 = out + ((size_t)(b * H_ + h0 + 1) * S_ + s) * HS_ + tx * 4;
        *(float4*)r0 = make_float4(acc[i][0], acc[i][1], acc[i][2], acc[i][3]);
        *(float4*)r1 = make_float4(acc[i][4], acc[i][5], acc[i][6], acc[i][7]);
    }
}

// ---------------------------------------------------------------------------
// Flash attention: 256 threads, 64-query tile, 64-key tiles.
// Both QK^T and PV are register-tiled 4x4 GEMMs. Q/K staged transposed [d][r].
// P overwrites the K buffer (XOR-swizzled) to stay within 48KB static smem.
// ---------------------------------------------------------------------------
__global__ __launch_bounds__(256) void attn_kernel() {
    const int qb = blockIdx.x;
    const int h  = blockIdx.y;
    const int b  = blockIdx.z;
    const size_t base = (size_t)(b * H_ + h) * S_ * HS_;
    const float* Q = g_q + base;
    const float* K = g_k + base;
    const float* V = g_v + base;
    float*       O = g_o + base;

    const int tid = threadIdx.x;
    const int tx  = tid & 15;    // key-col group / d-col group
    const int ty  = tid >> 4;    // query-row group

    __shared__ float Qs[64][64];  // [d][r]
    __shared__ float Ks[64][64];  // [d][j]; reused as P [t][r] (swizzled)
    __shared__ float Vs[64][64];  // [t][d]
    float* Ps = &Ks[0][0];

    // Load Q transposed + pre-scaled
    {
        const float* Qp = Q + (size_t)qb * 64 * HS_;
        int r = tid & 63;
        #pragma unroll
        for (int ii = 0; ii < 4; ii++) {
            int ch = (tid >> 6) + ii * 4;
            float4 t4 = *(const float4*)(Qp + r * HS_ + ch * 4);
            Qs[ch * 4 + 0][r] = t4.x * 0.125f;
            Qs[ch * 4 + 1][r] = t4.y * 0.125f;
            Qs[ch * 4 + 2][r] = t4.z * 0.125f;
            Qs[ch * 4 + 3][r] = t4.w * 0.125f;
        }
    }

    float m[4], l[4], o[4][4];
    #pragma unroll
    for (int i = 0; i < 4; i++) {
        m[i] = -1e30f; l[i] = 0.f;
        #pragma unroll
        for (int j = 0; j < 4; j++) o[i][j] = 0.f;
    }

    for (int kt = 0; kt <= qb; kt++) {
        __syncthreads();   // prior PV / Q-load complete before refilling Ks,Vs
        {
            const float* Kp = K + (size_t)kt * 64 * HS_;
            int r = tid & 63;
            #pragma unroll
            for (int ii = 0; ii < 4; ii++) {
                int ch = (tid >> 6) + ii * 4;
                float4 t4 = *(const float4*)(Kp + r * HS_ + ch * 4);
                Ks[ch * 4 + 0][r] = t4.x;
                Ks[ch * 4 + 1][r] = t4.y;
                Ks[ch * 4 + 2][r] = t4.z;
                Ks[ch * 4 + 3][r] = t4.w;
            }
            const float4* Vsrc = (const float4*)(V + (size_t)kt * 64 * HS_);
            #pragma unroll
            for (int ii = 0; ii < 4; ii++)
                ((float4*)Vs)[tid + ii * 256] = Vsrc[tid + ii * 256];
        }
        __syncthreads();

        // S tile: s[i][jj] = sum_d Qs[d][ty*4+i] * Ks[d][tx*4+jj]
        float s[4][4];
        #pragma unroll
        for (int i = 0; i < 4; i++)
            #pragma unroll
            for (int j = 0; j < 4; j++) s[i][j] = 0.f;

        #pragma unroll 8
        for (int d = 0; d < 64; d++) {
            float4 qa = *(const float4*)&Qs[d][ty * 4];
            float4 kb = *(const float4*)&Ks[d][tx * 4];
            float a[4] = {qa.x, qa.y, qa.z, qa.w};
            float c[4] = {kb.x, kb.y, kb.z, kb.w};
            #pragma unroll
            for (int i = 0; i < 4; i++)
                #pragma unroll
                for (int j = 0; j < 4; j++) s[i][j] += a[i] * c[j];
        }

        if (kt == qb) {   // causal mask on the diagonal tile
            #pragma unroll
            for (int i = 0; i < 4; i++)
                #pragma unroll
                for (int jj = 0; jj < 4; jj++)
                    if (tx * 4 + jj > ty * 4 + i) s[i][jj] = -1e30f;
        }

        // Online softmax (row reductions across the 16 tx lanes)
        #pragma unroll
        for (int i = 0; i < 4; i++) {
            float rm = fmaxf(fmaxf(s[i][0], s[i][1]), fmaxf(s[i][2], s[i][3]));
            #pragma unroll
            for (int off = 1; off < 16; off <<= 1)
                rm = fmaxf(rm, __shfl_xor_sync(0xffffffffu, rm, off));
            float mn   = fmaxf(m[i], rm);
            float corr = __expf(m[i] - mn);
            m[i] = mn;
            float rs = 0.f;
            #pragma unroll
            for (int jj = 0; jj < 4; jj++) {
                float p = __expf(s[i][jj] - mn);
                s[i][jj] = p;
                rs += p;
            }
            #pragma unroll
            for (int off = 1; off < 16; off <<= 1)
                rs += __shfl_xor_sync(0xffffffffu, rs, off);
            l[i] = l[i] * corr + rs;
            #pragma unroll
            for (int jj = 0; jj < 4; jj++) o[i][jj] *= corr;
        }

        __syncthreads();   // everyone done reading Ks before P overwrites it

        // Write P[t][r] into the Ks buffer, XOR-swizzled to dodge bank conflicts
        #pragma unroll
        for (int jj = 0; jj < 4; jj++) {
            int t   = tx * 4 + jj;
            int blk = ty ^ (t & 15);
            *(float4*)(Ps + t * 64 + blk * 4) =
                make_float4(s[0][jj], s[1][jj], s[2][jj], s[3][jj]);
        }
        __syncthreads();

        // O += P @ V : o[i][jj] += P[t][ty*4+i] * Vs[t][tx*4+jj]
        #pragma unroll 8
        for (int t = 0; t < 64; t++) {
            float4 pa = *(const float4*)(Ps + t * 64 + ((ty ^ (t & 15)) << 2));
            float4 vb = *(const float4*)&Vs[t][tx * 4];
            float a[4] = {pa.x, pa.y, pa.z, pa.w};
            float c[4] = {vb.x, vb.y, vb.z, vb.w};
            #pragma unroll
            for (int i = 0; i < 4; i++)
                #pragma unroll
                for (int j = 0; j < 4; j++) o[i][j] += a[i] * c[j];
        }
    }

    #pragma unroll
    for (int i = 0; i < 4; i++) {
        float inv = 1.f / l[i];
        int r = qb * 64 + ty * 4 + i;
        *(float4*)(O + (size_t)r * HS_ + tx * 4) =
            make_float4(o[i][0] * inv, o[i][1] * inv, o[i][2] * inv, o[i][3] * inv);
    }
}

// ---------------------------------------------------------------------------
// Output projection: 128x128x16 tiles, 8x8 per thread. A gathers head-concat.
// ---------------------------------------------------------------------------
__global__ __launch_bounds__(256) void proj_gemm(
    const float* __restrict__ bp, float* __restrict__ out)
{
    const int n0 = blockIdx.x * 128;
    const int m0 = blockIdx.y * 128;

    __shared__ float As[16][128];
    __shared__ float Bs[16][128];

    const int tid = threadIdx.x;
    const int tx  = tid & 15;
    const int ty  = tid >> 4;

    float acc[8][8];
    #pragma unroll
    for (int i = 0; i < 8; i++)
        #pragma unroll
        for (int j = 0; j < 8; j++) acc[i][j] = 0.f;

    for (int k0 = 0; k0 < C_; k0 += 16) {
        #pragma unroll
        for (int it = 0; it < 2; it++) {
            int ar  = it * 64 + (tid >> 2);
            int ac4 = tid & 3;
            int kg  = k0 + ac4 * 4;
            int m   = m0 + ar;
            int bb  = m >> 11;
            int ss  = m & 2047;
            float4 v = *(const float4*)(
                g_o + ((size_t)(bb * H_ + (kg >> 6)) * S_ + ss) * HS_ + (kg & 63));
            As[ac4 * 4 + 0][ar] = v.x;
            As[ac4 * 4 + 1][ar] = v.y;
            As[ac4 * 4 + 2][ar] = v.z;
            As[ac4 * 4 + 3][ar] = v.w;
        }
        #pragma unroll
        for (int it = 0; it < 2; it++) {
            int bk  = it * 8 + (tid >> 5);
            int bc4 = tid & 31;
            *(float4*)&Bs[bk][bc4 * 4] =
                *(const float4*)(g_WpT + (size_t)(k0 + bk) * C_ + n0 + bc4 * 4);
        }
        __syncthreads();

        #pragma unroll
        for (int k = 0; k < 16; k++) {
            float a[8], b[8];
            *(float4*)&a[0] = *(const float4*)&As[k][ty * 4];
            *(float4*)&a[4] = *(const float4*)&As[k][64 + ty * 4];
            *(float4*)&b[0] = *(const float4*)&Bs[k][tx * 4];
            *(float4*)&b[4] = *(const float4*)&Bs[k][64 + tx * 4];
            #pragma unroll
            for (int i = 0; i < 8; i++)
                #pragma unroll
                for (int j = 0; j < 8; j++) acc[i][j] += a[i] * b[j];
        }
        __syncthreads();
    }

    float4 bias0 = *(const float4*)(bp + n0 + tx * 4);
    float4 bias1 = *(const float4*)(bp + n0 + 64 + tx * 4);
    #pragma unroll
    for (int i = 0; i < 8; i++) {
        int m = m0 + ((i < 4) ? (ty * 4 + i) : (64 + ty * 4 + i - 4));
        *(float4*)(out + (size_t)m * C_ + n0 + tx * 4) =
            make_float4(acc[i][0] + bias0.x, acc[i][1] + bias0.y,
                        acc[i][2] + bias0.z, acc[i][3] + bias0.w);
        *(float4*)(out + (size_t)m * C_ + n0 + 64 + tx * 4) =
            make_float4(acc[i][4] + bias1.x, acc[i][5] + bias1.y,
                        acc[i][6] + bias1.z, acc[i][7] + bias1.w);
    }
}

// ---------------------------------------------------------------------------
extern "C" void kernel_launch(void* const* d_in, const int* in_sizes, int n_in,
                              void* d_out, int out_size) {
    const float* x  = (const float*)d_in[0];
    const float* Wq = (const float*)d_in[1];
    const float* Wk = (const float*)d_in[2];
    const float* Wv = (const float*)d_in[3];
    const float* Wp = (const float*)d_in[4];
    const float* bp = (const float*)d_in[5];
    float* out = (float*)d_out;

    transpose_wp_kernel<<<(C_ * C_) / 256, 256>>>(Wp);
    qkv_gemm<<<dim3(C_ / 128, M_ / 128, 3), 256>>>(x, Wq, Wk, Wv);
    attn_kernel<<<dim3(S_ / 64, H_, B_), 256>>>();
    proj_gemm<<<dim3(C_ / 128, M_ / 128), 256>>>(bp, out);
}

// round 4
// speedup vs baseline: 1.8093x; 1.4169x over previous
#include <cuda_runtime.h>
#include <cuda_bf16.h>
#include <cstdint>

constexpr int B_  = 4;
constexpr int S_  = 2048;
constexpr int C_  = 1024;
constexpr int H_  = 16;
constexpr int HS_ = 64;
constexpr int M_  = B_ * S_;                    // 8192
constexpr int QKV_ELEMS = B_ * H_ * S_ * HS_;   // 8388608
constexpr int KP_ = C_ / 2;                     // 512 packed k-pairs

__device__ float g_q[QKV_ELEMS];
__device__ float g_k[QKV_ELEMS];
__device__ float g_v[QKV_ELEMS];
__device__ float g_o[QKV_ELEMS];                    // attention output [B,H,S,HS]
__device__ uint32_t g_whi[3 * C_ * KP_];            // [mat][n][kp] packed bf16 pairs
__device__ uint32_t g_wlo[3 * C_ * KP_];
__device__ uint32_t g_phi[C_ * KP_];                // [n][kp] for Wp^T
__device__ uint32_t g_plo[C_ * KP_];

// ---------------------------------------------------------------------------
__device__ __forceinline__ uint32_t pack2(__nv_bfloat16 a, __nv_bfloat16 b) {
    __nv_bfloat162 t; t.x = a; t.y = b;   // low half = first (even) k
    return *reinterpret_cast<uint32_t*>(&t);
}
__device__ __forceinline__ void decomp2(float a, float b, uint32_t& hi, uint32_t& lo) {
    __nv_bfloat16 ha = __float2bfloat16(a);
    __nv_bfloat16 hb = __float2bfloat16(b);
    __nv_bfloat16 la = __float2bfloat16(a - __bfloat162float(ha));
    __nv_bfloat16 lb = __float2bfloat16(b - __bfloat162float(hb));
    hi = pack2(ha, hb);
    lo = pack2(la, lb);
}

// mma.m16n8k16 bf16: D(16x8,f32) += A(16x16) * B(16x8)
__device__ __forceinline__ void mma_bf16(float* d, const uint32_t* a, const uint32_t* b) {
    asm volatile(
        "mma.sync.aligned.m16n8k16.row.col.f32.bf16.bf16.f32 "
        "{%0,%1,%2,%3}, {%4,%5,%6,%7}, {%8,%9}, {%0,%1,%2,%3};\n"
        : "+f"(d[0]), "+f"(d[1]), "+f"(d[2]), "+f"(d[3])
        : "r"(a[0]), "r"(a[1]), "r"(a[2]), "r"(a[3]), "r"(b[0]), "r"(b[1]));
}

// ---------------------------------------------------------------------------
// Weight pack: W[h][k][d] -> g_whi/lo[mat][n=h*64+d][kp] (bf16 pair over k)
// ---------------------------------------------------------------------------
__global__ void pack_w_kernel(const float* __restrict__ Wq,
                              const float* __restrict__ Wk,
                              const float* __restrict__ Wv) {
    int idx = blockIdx.x * 256 + threadIdx.x;       // 3*1024*512
    int mat = idx / (C_ * KP_);
    int rem = idx - mat * (C_ * KP_);
    int n   = rem >> 9;
    int kp  = rem & 511;
    const float* W = (mat == 0) ? Wq : (mat == 1) ? Wk : Wv;
    int h = n >> 6, d = n & 63;
    const float* base = W + (size_t)h * C_ * HS_ + (size_t)(2 * kp) * HS_ + d;
    float f0 = base[0];
    float f1 = base[HS_];
    uint32_t hi, lo;
    decomp2(f0, f1, hi, lo);
    g_whi[(size_t)mat * C_ * KP_ + (size_t)n * KP_ + kp] = hi;
    g_wlo[(size_t)mat * C_ * KP_ + (size_t)n * KP_ + kp] = lo;
}

// Wp pack: proj B[k][n] = Wp[n][k]; pair over k is contiguous in Wp rows.
__global__ void pack_wp_kernel(const float* __restrict__ Wp) {
    int idx = blockIdx.x * 256 + threadIdx.x;       // 1024*512
    int n  = idx >> 9;
    int kp = idx & 511;
    float2 f = *(const float2*)(Wp + (size_t)n * C_ + 2 * kp);
    uint32_t hi, lo;
    decomp2(f.x, f.y, hi, lo);
    g_phi[(size_t)n * KP_ + kp] = hi;
    g_plo[(size_t)n * KP_ + kp] = lo;
}

// ---------------------------------------------------------------------------
// Shared GEMM core: 128x128x32 tiles, 8 warps (2m x 4n), warp tile 64x32.
// bf16x2 split: acc += Ah*Bh + Ah*Bl + Al*Bh.
// Smem packed-pair layout, row stride 20 uint32 (conflict-free fragments).
// ---------------------------------------------------------------------------
constexpr int PSTR = 20;

struct Frag { float acc[4][4][4]; };

__device__ __forceinline__ void gemm_compute(
    const uint32_t* Ah, const uint32_t* Al,
    const uint32_t* Bh, const uint32_t* Bl,
    int wm, int wn, int gid, int tig, float acc[4][4][4])
{
    #pragma unroll
    for (int ks = 0; ks < 2; ks++) {
        const int kb = ks * 8;
        uint32_t ah[4][4], al[4][4], bh[4][2], bl[4][2];
        #pragma unroll
        for (int mt = 0; mt < 4; mt++) {
            int r = wm + mt * 16 + gid;
            ah[mt][0] = Ah[r * PSTR + kb + tig];
            ah[mt][1] = Ah[(r + 8) * PSTR + kb + tig];
            ah[mt][2] = Ah[r * PSTR + kb + tig + 4];
            ah[mt][3] = Ah[(r + 8) * PSTR + kb + tig + 4];
            al[mt][0] = Al[r * PSTR + kb + tig];
            al[mt][1] = Al[(r + 8) * PSTR + kb + tig];
            al[mt][2] = Al[r * PSTR + kb + tig + 4];
            al[mt][3] = Al[(r + 8) * PSTR + kb + tig + 4];
        }
        #pragma unroll
        for (int nt = 0; nt < 4; nt++) {
            int n = wn + nt * 8 + gid;
            bh[nt][0] = Bh[n * PSTR + kb + tig];
            bh[nt][1] = Bh[n * PSTR + kb + tig + 4];
            bl[nt][0] = Bl[n * PSTR + kb + tig];
            bl[nt][1] = Bl[n * PSTR + kb + tig + 4];
        }
        #pragma unroll
        for (int mt = 0; mt < 4; mt++)
            #pragma unroll
            for (int nt = 0; nt < 4; nt++) {
                mma_bf16(acc[mt][nt], ah[mt], bh[nt]);
                mma_bf16(acc[mt][nt], ah[mt], bl[nt]);
                mma_bf16(acc[mt][nt], al[mt], bh[nt]);
            }
    }
}

// ---------------------------------------------------------------------------
// QKV GEMM: A = x (fp32, decomposed on the fly), B = packed weights.
// ---------------------------------------------------------------------------
__global__ __launch_bounds__(256, 2) void qkv_gemm(const float* __restrict__ x) {
    const int mat = blockIdx.z;
    float* out = (mat == 0) ? g_q : (mat == 1) ? g_k : g_v;
    const uint32_t* Whi = g_whi + (size_t)mat * C_ * KP_;
    const uint32_t* Wlo = g_wlo + (size_t)mat * C_ * KP_;

    const int n0 = blockIdx.x * 128;
    const int m0 = blockIdx.y * 128;

    __shared__ uint32_t Ah[128 * PSTR], Al[128 * PSTR];
    __shared__ uint32_t Bh[128 * PSTR], Bl[128 * PSTR];

    const int tid  = threadIdx.x;
    const int warp = tid >> 5;
    const int lane = tid & 31;
    const int gid  = lane >> 2;
    const int tig  = lane & 3;
    const int wm   = (warp & 1) * 64;
    const int wn   = (warp >> 1) * 32;

    float acc[4][4][4];
    #pragma unroll
    for (int mt = 0; mt < 4; mt++)
        #pragma unroll
        for (int nt = 0; nt < 4; nt++)
            #pragma unroll
            for (int e = 0; e < 4; e++) acc[mt][nt][e] = 0.f;

    for (int k0 = 0; k0 < C_; k0 += 32) {
        const int kp0 = k0 >> 1;
        // A: 128x32 fp32 -> packed pairs
        #pragma unroll
        for (int i = 0; i < 4; i++) {
            int lin = i * 256 + tid;
            int row = lin >> 3, c4 = lin & 7;
            float4 v = *(const float4*)(x + (size_t)(m0 + row) * C_ + k0 + c4 * 4);
            uint32_t h0, l0, h1, l1;
            decomp2(v.x, v.y, h0, l0);
            decomp2(v.z, v.w, h1, l1);
            Ah[row * PSTR + c4 * 2]     = h0;
            Ah[row * PSTR + c4 * 2 + 1] = h1;
            Al[row * PSTR + c4 * 2]     = l0;
            Al[row * PSTR + c4 * 2 + 1] = l1;
        }
        // B: prepacked gmem [n][kp]
        #pragma unroll
        for (int i = 0; i < 2; i++) {
            int lin = i * 256 + tid;
            int n = lin >> 2, kq = lin & 3;
            uint4 vh = *(const uint4*)(Whi + (size_t)(n0 + n) * KP_ + kp0 + kq * 4);
            uint4 vl = *(const uint4*)(Wlo + (size_t)(n0 + n) * KP_ + kp0 + kq * 4);
            Bh[n * PSTR + kq * 4 + 0] = vh.x;
            Bh[n * PSTR + kq * 4 + 1] = vh.y;
            Bh[n * PSTR + kq * 4 + 2] = vh.z;
            Bh[n * PSTR + kq * 4 + 3] = vh.w;
            Bl[n * PSTR + kq * 4 + 0] = vl.x;
            Bl[n * PSTR + kq * 4 + 1] = vl.y;
            Bl[n * PSTR + kq * 4 + 2] = vl.z;
            Bl[n * PSTR + kq * 4 + 3] = vl.w;
        }
        __syncthreads();
        gemm_compute(Ah, Al, Bh, Bl, wm, wn, gid, tig, acc);
        __syncthreads();
    }

    // Epilogue: [b,h,s,d] layout.
    #pragma unroll
    for (int mt = 0; mt < 4; mt++) {
        int r  = m0 + wm + mt * 16 + gid;
        int b  = r >> 11;
        int s0 = r & 2047;
        #pragma unroll
        for (int nt = 0; nt < 4; nt++) {
            int n    = n0 + wn + nt * 8 + 2 * tig;
            int head = n >> 6;
            int d    = n & 63;
            float* p0 = out + ((size_t)(b * H_ + head) * S_ + s0) * HS_ + d;
            *(float2*)p0             = make_float2(acc[mt][nt][0], acc[mt][nt][1]);
            *(float2*)(p0 + 8 * HS_) = make_float2(acc[mt][nt][2], acc[mt][nt][3]);
        }
    }
}

// ---------------------------------------------------------------------------
// Projection GEMM: A = g_o (head-concat gather, fp32), B = packed Wp^T.
// ---------------------------------------------------------------------------
__global__ __launch_bounds__(256, 2) void proj_gemm(
    const float* __restrict__ bp, float* __restrict__ out)
{
    const int n0 = blockIdx.x * 128;
    const int m0 = blockIdx.y * 128;

    __shared__ uint32_t Ah[128 * PSTR], Al[128 * PSTR];
    __shared__ uint32_t Bh[128 * PSTR], Bl[128 * PSTR];

    const int tid  = threadIdx.x;
    const int warp = tid >> 5;
    const int lane = tid & 31;
    const int gid  = lane >> 2;
    const int tig  = lane & 3;
    const int wm   = (warp & 1) * 64;
    const int wn   = (warp >> 1) * 32;

    float acc[4][4][4];
    #pragma unroll
    for (int mt = 0; mt < 4; mt++)
        #pragma unroll
        for (int nt = 0; nt < 4; nt++)
            #pragma unroll
            for (int e = 0; e < 4; e++) acc[mt][nt][e] = 0.f;

    for (int k0 = 0; k0 < C_; k0 += 32) {
        const int kp0 = k0 >> 1;
        #pragma unroll
        for (int i = 0; i < 4; i++) {
            int lin = i * 256 + tid;
            int row = lin >> 3, c4 = lin & 7;
            int m   = m0 + row;
            int bb  = m >> 11;
            int ss  = m & 2047;
            int kg  = k0 + c4 * 4;
            float4 v = *(const float4*)(
                g_o + ((size_t)(bb * H_ + (kg >> 6)) * S_ + ss) * HS_ + (kg & 63));
            uint32_t h0, l0, h1, l1;
            decomp2(v.x, v.y, h0, l0);
            decomp2(v.z, v.w, h1, l1);
            Ah[row * PSTR + c4 * 2]     = h0;
            Ah[row * PSTR + c4 * 2 + 1] = h1;
            Al[row * PSTR + c4 * 2]     = l0;
            Al[row * PSTR + c4 * 2 + 1] = l1;
        }
        #pragma unroll
        for (int i = 0; i < 2; i++) {
            int lin = i * 256 + tid;
            int n = lin >> 2, kq = lin & 3;
            uint4 vh = *(const uint4*)(g_phi + (size_t)(n0 + n) * KP_ + kp0 + kq * 4);
            uint4 vl = *(const uint4*)(g_plo + (size_t)(n0 + n) * KP_ + kp0 + kq * 4);
            Bh[n * PSTR + kq * 4 + 0] = vh.x;
            Bh[n * PSTR + kq * 4 + 1] = vh.y;
            Bh[n * PSTR + kq * 4 + 2] = vh.z;
            Bh[n * PSTR + kq * 4 + 3] = vh.w;
            Bl[n * PSTR + kq * 4 + 0] = vl.x;
            Bl[n * PSTR + kq * 4 + 1] = vl.y;
            Bl[n * PSTR + kq * 4 + 2] = vl.z;
            Bl[n * PSTR + kq * 4 + 3] = vl.w;
        }
        __syncthreads();
        gemm_compute(Ah, Al, Bh, Bl, wm, wn, gid, tig, acc);
        __syncthreads();
    }

    #pragma unroll
    for (int mt = 0; mt < 4; mt++) {
        int r = m0 + wm + mt * 16 + gid;
        #pragma unroll
        for (int nt = 0; nt < 4; nt++) {
            int n = n0 + wn + nt * 8 + 2 * tig;
            float2 bias = *(const float2*)(bp + n);
            *(float2*)(out + (size_t)r * C_ + n) =
                make_float2(acc[mt][nt][0] + bias.x, acc[mt][nt][1] + bias.y);
            *(float2*)(out + (size_t)(r + 8) * C_ + n) =
                make_float2(acc[mt][nt][2] + bias.x, acc[mt][nt][3] + bias.y);
        }
    }
}

// ---------------------------------------------------------------------------
// Flash attention (scalar fp32, unchanged — known good).
// ---------------------------------------------------------------------------
__global__ __launch_bounds__(256) void attn_kernel() {
    const int qb = blockIdx.x;
    const int h  = blockIdx.y;
    const int b  = blockIdx.z;
    const size_t base = (size_t)(b * H_ + h) * S_ * HS_;
    const float* Q = g_q + base;
    const float* K = g_k + base;
    const float* V = g_v + base;
    float*       O = g_o + base;

    const int tid = threadIdx.x;
    const int tx  = tid & 15;
    const int ty  = tid >> 4;

    __shared__ float Qs[64][64];
    __shared__ float Ks[64][64];
    __shared__ float Vs[64][64];
    float* Ps = &Ks[0][0];

    {
        const float* Qp = Q + (size_t)qb * 64 * HS_;
        int r = tid & 63;
        #pragma unroll
        for (int ii = 0; ii < 4; ii++) {
            int ch = (tid >> 6) + ii * 4;
            float4 t4 = *(const float4*)(Qp + r * HS_ + ch * 4);
            Qs[ch * 4 + 0][r] = t4.x * 0.125f;
            Qs[ch * 4 + 1][r] = t4.y * 0.125f;
            Qs[ch * 4 + 2][r] = t4.z * 0.125f;
            Qs[ch * 4 + 3][r] = t4.w * 0.125f;
        }
    }

    float m[4], l[4], o[4][4];
    #pragma unroll
    for (int i = 0; i < 4; i++) {
        m[i] = -1e30f; l[i] = 0.f;
        #pragma unroll
        for (int j = 0; j < 4; j++) o[i][j] = 0.f;
    }

    for (int kt = 0; kt <= qb; kt++) {
        __syncthreads();
        {
            const float* Kp = K + (size_t)kt * 64 * HS_;
            int r = tid & 63;
            #pragma unroll
            for (int ii = 0; ii < 4; ii++) {
                int ch = (tid >> 6) + ii * 4;
                float4 t4 = *(const float4*)(Kp + r * HS_ + ch * 4);
                Ks[ch * 4 + 0][r] = t4.x;
                Ks[ch * 4 + 1][r] = t4.y;
                Ks[ch * 4 + 2][r] = t4.z;
                Ks[ch * 4 + 3][r] = t4.w;
            }
            const float4* Vsrc = (const float4*)(V + (size_t)kt * 64 * HS_);
            #pragma unroll
            for (int ii = 0; ii < 4; ii++)
                ((float4*)Vs)[tid + ii * 256] = Vsrc[tid + ii * 256];
        }
        __syncthreads();

        float s[4][4];
        #pragma unroll
        for (int i = 0; i < 4; i++)
            #pragma unroll
            for (int j = 0; j < 4; j++) s[i][j] = 0.f;

        #pragma unroll 8
        for (int d = 0; d < 64; d++) {
            float4 qa = *(const float4*)&Qs[d][ty * 4];
            float4 kb = *(const float4*)&Ks[d][tx * 4];
            float a[4] = {qa.x, qa.y, qa.z, qa.w};
            float c[4] = {kb.x, kb.y, kb.z, kb.w};
            #pragma unroll
            for (int i = 0; i < 4; i++)
                #pragma unroll
                for (int j = 0; j < 4; j++) s[i][j] += a[i] * c[j];
        }

        if (kt == qb) {
            #pragma unroll
            for (int i = 0; i < 4; i++)
                #pragma unroll
                for (int jj = 0; jj < 4; jj++)
                    if (tx * 4 + jj > ty * 4 + i) s[i][jj] = -1e30f;
        }

        #pragma unroll
        for (int i = 0; i < 4; i++) {
            float rm = fmaxf(fmaxf(s[i][0], s[i][1]), fmaxf(s[i][2], s[i][3]));
            #pragma unroll
            for (int off = 1; off < 16; off <<= 1)
                rm = fmaxf(rm, __shfl_xor_sync(0xffffffffu, rm, off));
            float mn   = fmaxf(m[i], rm);
            float corr = __expf(m[i] - mn);
            m[i] = mn;
            float rs = 0.f;
            #pragma unroll
            for (int jj = 0; jj < 4; jj++) {
                float p = __expf(s[i][jj] - mn);
                s[i][jj] = p;
                rs += p;
            }
            #pragma unroll
            for (int off = 1; off < 16; off <<= 1)
                rs += __shfl_xor_sync(0xffffffffu, rs, off);
            l[i] = l[i] * corr + rs;
            #pragma unroll
            for (int jj = 0; jj < 4; jj++) o[i][jj] *= corr;
        }

        __syncthreads();

        #pragma unroll
        for (int jj = 0; jj < 4; jj++) {
            int t   = tx * 4 + jj;
            int blk = ty ^ (t & 15);
            *(float4*)(Ps + t * 64 + blk * 4) =
                make_float4(s[0][jj], s[1][jj], s[2][jj], s[3][jj]);
        }
        __syncthreads();

        #pragma unroll 8
        for (int t = 0; t < 64; t++) {
            float4 pa = *(const float4*)(Ps + t * 64 + ((ty ^ (t & 15)) << 2));
            float4 vb = *(const float4*)&Vs[t][tx * 4];
            float a[4] = {pa.x, pa.y, pa.z, pa.w};
            float c[4] = {vb.x, vb.y, vb.z, vb.w};
            #pragma unroll
            for (int i = 0; i < 4; i++)
                #pragma unroll
                for (int j = 0; j < 4; j++) o[i][j] += a[i] * c[j];
        }
    }

    #pragma unroll
    for (int i = 0; i < 4; i++) {
        float inv = 1.f / l[i];
        int r = qb * 64 + ty * 4 + i;
        *(float4*)(O + (size_t)r * HS_ + tx * 4) =
            make_float4(o[i][0] * inv, o[i][1] * inv, o[i][2] * inv, o[i][3] * inv);
    }
}

// ---------------------------------------------------------------------------
extern "C" void kernel_launch(void* const* d_in, const int* in_sizes, int n_in,
                              void* d_out, int out_size) {
    const float* x  = (const float*)d_in[0];
    const float* Wq = (const float*)d_in[1];
    const float* Wk = (const float*)d_in[2];
    const float* Wv = (const float*)d_in[3];
    const float* Wp = (const float*)d_in[4];
    const float* bp = (const float*)d_in[5];
    float* out = (float*)d_out;

    pack_w_kernel<<<(3 * C_ * KP_) / 256, 256>>>(Wq, Wk, Wv);
    pack_wp_kernel<<<(C_ * KP_) / 256, 256>>>(Wp);
    qkv_gemm<<<dim3(C_ / 128, M_ / 128, 3), 256>>>(x);
    attn_kernel<<<dim3(S_ / 64, H_, B_), 256>>>();
    proj_gemm<<<dim3(C_ / 128, M_ / 128), 256>>>(bp, out);
}

// round 5
// speedup vs baseline: 2.9382x; 1.6239x over previous
#include <cuda_runtime.h>
#include <cuda_bf16.h>
#include <cstdint>

constexpr int B_  = 4;
constexpr int S_  = 2048;
constexpr int C_  = 1024;
constexpr int H_  = 16;
constexpr int HS_ = 64;
constexpr int M_  = B_ * S_;                    // 8192
constexpr int QKV_ELEMS = B_ * H_ * S_ * HS_;   // 8388608
constexpr int KP_ = C_ / 2;                     // 512 packed k-pairs

__device__ float g_q[QKV_ELEMS];
__device__ float g_k[QKV_ELEMS];
__device__ float g_v[QKV_ELEMS];
__device__ float g_o[QKV_ELEMS];                    // attention output [B,H,S,HS]
__device__ uint32_t g_whi[3 * C_ * KP_];            // [mat][n][kp] packed bf16 pairs
__device__ uint32_t g_wlo[3 * C_ * KP_];
__device__ uint32_t g_phi[C_ * KP_];                // [n][kp] for Wp^T
__device__ uint32_t g_plo[C_ * KP_];

// ---------------------------------------------------------------------------
__device__ __forceinline__ uint32_t pack2(__nv_bfloat16 a, __nv_bfloat16 b) {
    __nv_bfloat162 t; t.x = a; t.y = b;   // low half = first (even) k
    return *reinterpret_cast<uint32_t*>(&t);
}
__device__ __forceinline__ void decomp2(float a, float b, uint32_t& hi, uint32_t& lo) {
    __nv_bfloat16 ha = __float2bfloat16(a);
    __nv_bfloat16 hb = __float2bfloat16(b);
    __nv_bfloat16 la = __float2bfloat16(a - __bfloat162float(ha));
    __nv_bfloat16 lb = __float2bfloat16(b - __bfloat162float(hb));
    hi = pack2(ha, hb);
    lo = pack2(la, lb);
}

// mma.m16n8k16 bf16: D(16x8,f32) += A(16x16) * B(16x8)
__device__ __forceinline__ void mma_bf16(float* d, const uint32_t* a, const uint32_t* b) {
    asm volatile(
        "mma.sync.aligned.m16n8k16.row.col.f32.bf16.bf16.f32 "
        "{%0,%1,%2,%3}, {%4,%5,%6,%7}, {%8,%9}, {%0,%1,%2,%3};\n"
        : "+f"(d[0]), "+f"(d[1]), "+f"(d[2]), "+f"(d[3])
        : "r"(a[0]), "r"(a[1]), "r"(a[2]), "r"(a[3]), "r"(b[0]), "r"(b[1]));
}

// ---------------------------------------------------------------------------
// Weight pack: W[h][k][d] -> g_whi/lo[mat][n=h*64+d][kp] (bf16 pair over k)
// ---------------------------------------------------------------------------
__global__ void pack_w_kernel(const float* __restrict__ Wq,
                              const float* __restrict__ Wk,
                              const float* __restrict__ Wv) {
    int idx = blockIdx.x * 256 + threadIdx.x;       // 3*1024*512
    int mat = idx / (C_ * KP_);
    int rem = idx - mat * (C_ * KP_);
    int n   = rem >> 9;
    int kp  = rem & 511;
    const float* W = (mat == 0) ? Wq : (mat == 1) ? Wk : Wv;
    int h = n >> 6, d = n & 63;
    const float* base = W + (size_t)h * C_ * HS_ + (size_t)(2 * kp) * HS_ + d;
    float f0 = base[0];
    float f1 = base[HS_];
    uint32_t hi, lo;
    decomp2(f0, f1, hi, lo);
    g_whi[(size_t)mat * C_ * KP_ + (size_t)n * KP_ + kp] = hi;
    g_wlo[(size_t)mat * C_ * KP_ + (size_t)n * KP_ + kp] = lo;
}

__global__ void pack_wp_kernel(const float* __restrict__ Wp) {
    int idx = blockIdx.x * 256 + threadIdx.x;       // 1024*512
    int n  = idx >> 9;
    int kp = idx & 511;
    float2 f = *(const float2*)(Wp + (size_t)n * C_ + 2 * kp);
    uint32_t hi, lo;
    decomp2(f.x, f.y, hi, lo);
    g_phi[(size_t)n * KP_ + kp] = hi;
    g_plo[(size_t)n * KP_ + kp] = lo;
}

// ---------------------------------------------------------------------------
// GEMM core (unchanged from round 4): 128x128x32, 8 warps, bf16x2 split.
// ---------------------------------------------------------------------------
constexpr int PSTR = 20;

__device__ __forceinline__ void gemm_compute(
    const uint32_t* Ah, const uint32_t* Al,
    const uint32_t* Bh, const uint32_t* Bl,
    int wm, int wn, int gid, int tig, float acc[4][4][4])
{
    #pragma unroll
    for (int ks = 0; ks < 2; ks++) {
        const int kb = ks * 8;
        uint32_t ah[4][4], al[4][4], bh[4][2], bl[4][2];
        #pragma unroll
        for (int mt = 0; mt < 4; mt++) {
            int r = wm + mt * 16 + gid;
            ah[mt][0] = Ah[r * PSTR + kb + tig];
            ah[mt][1] = Ah[(r + 8) * PSTR + kb + tig];
            ah[mt][2] = Ah[r * PSTR + kb + tig + 4];
            ah[mt][3] = Ah[(r + 8) * PSTR + kb + tig + 4];
            al[mt][0] = Al[r * PSTR + kb + tig];
            al[mt][1] = Al[(r + 8) * PSTR + kb + tig];
            al[mt][2] = Al[r * PSTR + kb + tig + 4];
            al[mt][3] = Al[(r + 8) * PSTR + kb + tig + 4];
        }
        #pragma unroll
        for (int nt = 0; nt < 4; nt++) {
            int n = wn + nt * 8 + gid;
            bh[nt][0] = Bh[n * PSTR + kb + tig];
            bh[nt][1] = Bh[n * PSTR + kb + tig + 4];
            bl[nt][0] = Bl[n * PSTR + kb + tig];
            bl[nt][1] = Bl[n * PSTR + kb + tig + 4];
        }
        #pragma unroll
        for (int mt = 0; mt < 4; mt++)
            #pragma unroll
            for (int nt = 0; nt < 4; nt++) {
                mma_bf16(acc[mt][nt], ah[mt], bh[nt]);
                mma_bf16(acc[mt][nt], ah[mt], bl[nt]);
                mma_bf16(acc[mt][nt], al[mt], bh[nt]);
            }
    }
}

// ---------------------------------------------------------------------------
__global__ __launch_bounds__(256, 2) void qkv_gemm(const float* __restrict__ x) {
    const int mat = blockIdx.z;
    float* out = (mat == 0) ? g_q : (mat == 1) ? g_k : g_v;
    const uint32_t* Whi = g_whi + (size_t)mat * C_ * KP_;
    const uint32_t* Wlo = g_wlo + (size_t)mat * C_ * KP_;

    const int n0 = blockIdx.x * 128;
    const int m0 = blockIdx.y * 128;

    __shared__ uint32_t Ah[128 * PSTR], Al[128 * PSTR];
    __shared__ uint32_t Bh[128 * PSTR], Bl[128 * PSTR];

    const int tid  = threadIdx.x;
    const int warp = tid >> 5;
    const int lane = tid & 31;
    const int gid  = lane >> 2;
    const int tig  = lane & 3;
    const int wm   = (warp & 1) * 64;
    const int wn   = (warp >> 1) * 32;

    float acc[4][4][4];
    #pragma unroll
    for (int mt = 0; mt < 4; mt++)
        #pragma unroll
        for (int nt = 0; nt < 4; nt++)
            #pragma unroll
            for (int e = 0; e < 4; e++) acc[mt][nt][e] = 0.f;

    for (int k0 = 0; k0 < C_; k0 += 32) {
        const int kp0 = k0 >> 1;
        #pragma unroll
        for (int i = 0; i < 4; i++) {
            int lin = i * 256 + tid;
            int row = lin >> 3, c4 = lin & 7;
            float4 v = *(const float4*)(x + (size_t)(m0 + row) * C_ + k0 + c4 * 4);
            uint32_t h0, l0, h1, l1;
            decomp2(v.x, v.y, h0, l0);
            decomp2(v.z, v.w, h1, l1);
            Ah[row * PSTR + c4 * 2]     = h0;
            Ah[row * PSTR + c4 * 2 + 1] = h1;
            Al[row * PSTR + c4 * 2]     = l0;
            Al[row * PSTR + c4 * 2 + 1] = l1;
        }
        #pragma unroll
        for (int i = 0; i < 2; i++) {
            int lin = i * 256 + tid;
            int n = lin >> 2, kq = lin & 3;
            uint4 vh = *(const uint4*)(Whi + (size_t)(n0 + n) * KP_ + kp0 + kq * 4);
            uint4 vl = *(const uint4*)(Wlo + (size_t)(n0 + n) * KP_ + kp0 + kq * 4);
            Bh[n * PSTR + kq * 4 + 0] = vh.x;
            Bh[n * PSTR + kq * 4 + 1] = vh.y;
            Bh[n * PSTR + kq * 4 + 2] = vh.z;
            Bh[n * PSTR + kq * 4 + 3] = vh.w;
            Bl[n * PSTR + kq * 4 + 0] = vl.x;
            Bl[n * PSTR + kq * 4 + 1] = vl.y;
            Bl[n * PSTR + kq * 4 + 2] = vl.z;
            Bl[n * PSTR + kq * 4 + 3] = vl.w;
        }
        __syncthreads();
        gemm_compute(Ah, Al, Bh, Bl, wm, wn, gid, tig, acc);
        __syncthreads();
    }

    #pragma unroll
    for (int mt = 0; mt < 4; mt++) {
        int r  = m0 + wm + mt * 16 + gid;
        int b  = r >> 11;
        int s0 = r & 2047;
        #pragma unroll
        for (int nt = 0; nt < 4; nt++) {
            int n    = n0 + wn + nt * 8 + 2 * tig;
            int head = n >> 6;
            int d    = n & 63;
            float* p0 = out + ((size_t)(b * H_ + head) * S_ + s0) * HS_ + d;
            *(float2*)p0             = make_float2(acc[mt][nt][0], acc[mt][nt][1]);
            *(float2*)(p0 + 8 * HS_) = make_float2(acc[mt][nt][2], acc[mt][nt][3]);
        }
    }
}

// ---------------------------------------------------------------------------
__global__ __launch_bounds__(256, 2) void proj_gemm(
    const float* __restrict__ bp, float* __restrict__ out)
{
    const int n0 = blockIdx.x * 128;
    const int m0 = blockIdx.y * 128;

    __shared__ uint32_t Ah[128 * PSTR], Al[128 * PSTR];
    __shared__ uint32_t Bh[128 * PSTR], Bl[128 * PSTR];

    const int tid  = threadIdx.x;
    const int warp = tid >> 5;
    const int lane = tid & 31;
    const int gid  = lane >> 2;
    const int tig  = lane & 3;
    const int wm   = (warp & 1) * 64;
    const int wn   = (warp >> 1) * 32;

    float acc[4][4][4];
    #pragma unroll
    for (int mt = 0; mt < 4; mt++)
        #pragma unroll
        for (int nt = 0; nt < 4; nt++)
            #pragma unroll
            for (int e = 0; e < 4; e++) acc[mt][nt][e] = 0.f;

    for (int k0 = 0; k0 < C_; k0 += 32) {
        const int kp0 = k0 >> 1;
        #pragma unroll
        for (int i = 0; i < 4; i++) {
            int lin = i * 256 + tid;
            int row = lin >> 3, c4 = lin & 7;
            int m   = m0 + row;
            int bb  = m >> 11;
            int ss  = m & 2047;
            int kg  = k0 + c4 * 4;
            float4 v = *(const float4*)(
                g_o + ((size_t)(bb * H_ + (kg >> 6)) * S_ + ss) * HS_ + (kg & 63));
            uint32_t h0, l0, h1, l1;
            decomp2(v.x, v.y, h0, l0);
            decomp2(v.z, v.w, h1, l1);
            Ah[row * PSTR + c4 * 2]     = h0;
            Ah[row * PSTR + c4 * 2 + 1] = h1;
            Al[row * PSTR + c4 * 2]     = l0;
            Al[row * PSTR + c4 * 2 + 1] = l1;
        }
        #pragma unroll
        for (int i = 0; i < 2; i++) {
            int lin = i * 256 + tid;
            int n = lin >> 2, kq = lin & 3;
            uint4 vh = *(const uint4*)(g_phi + (size_t)(n0 + n) * KP_ + kp0 + kq * 4);
            uint4 vl = *(const uint4*)(g_plo + (size_t)(n0 + n) * KP_ + kp0 + kq * 4);
            Bh[n * PSTR + kq * 4 + 0] = vh.x;
            Bh[n * PSTR + kq * 4 + 1] = vh.y;
            Bh[n * PSTR + kq * 4 + 2] = vh.z;
            Bh[n * PSTR + kq * 4 + 3] = vh.w;
            Bl[n * PSTR + kq * 4 + 0] = vl.x;
            Bl[n * PSTR + kq * 4 + 1] = vl.y;
            Bl[n * PSTR + kq * 4 + 2] = vl.z;
            Bl[n * PSTR + kq * 4 + 3] = vl.w;
        }
        __syncthreads();
        gemm_compute(Ah, Al, Bh, Bl, wm, wn, gid, tig, acc);
        __syncthreads();
    }

    #pragma unroll
    for (int mt = 0; mt < 4; mt++) {
        int r = m0 + wm + mt * 16 + gid;
        #pragma unroll
        for (int nt = 0; nt < 4; nt++) {
            int n = n0 + wn + nt * 8 + 2 * tig;
            float2 bias = *(const float2*)(bp + n);
            *(float2*)(out + (size_t)r * C_ + n) =
                make_float2(acc[mt][nt][0] + bias.x, acc[mt][nt][1] + bias.y);
            *(float2*)(out + (size_t)(r + 8) * C_ + n) =
                make_float2(acc[mt][nt][2] + bias.x, acc[mt][nt][3] + bias.y);
        }
    }
}

// ---------------------------------------------------------------------------
// Flash attention on tensor cores, bf16x2 split numerics.
// 128-query tile, 8 warps (16 q-rows each), 64-key tiles.
// Q hi/lo fragments live in registers; K/V hi/lo in smem (stride-36 layout).
// P reused directly from score fragments as the PV A-operand.
// ---------------------------------------------------------------------------
constexpr int ATSTR = 36;   // smem row stride (uint32): banks = 4*gid+tig, conflict-free

__global__ __launch_bounds__(256) void attn_kernel() {
    const int qb = blockIdx.x;          // 128-query block
    const int h  = blockIdx.y;
    const int b  = blockIdx.z;
    const size_t base = (size_t)(b * H_ + h) * S_ * HS_;
    const float* Q = g_q + base;
    const float* K = g_k + base;
    const float* V = g_v + base;
    float*       O = g_o + base;

    const int tid  = threadIdx.x;
    const int warp = tid >> 5;
    const int lane = tid & 31;
    const int gid  = lane >> 2;
    const int tig  = lane & 3;
    const int wm   = warp * 16;         // warp's q rows within the 128 tile

    __shared__ uint32_t Kh[64 * ATSTR], Kl[64 * ATSTR];
    __shared__ uint32_t Vh[64 * ATSTR], Vl[64 * ATSTR];

    // ---- Stage Q (scaled by 0.125) into register fragments, via Kh/Kl ----
    uint32_t qh[4][4], ql[4][4];
    #pragma unroll
    for (int p = 0; p < 2; p++) {
        #pragma unroll
        for (int i = 0; i < 4; i++) {
            int lin = i * 256 + tid;
            int row = lin >> 4, f4 = lin & 15;
            float4 v = *(const float4*)(
                Q + (size_t)(qb * 128 + p * 64 + row) * HS_ + f4 * 4);
            uint32_t h0, l0, h1, l1;
            decomp2(v.x * 0.125f, v.y * 0.125f, h0, l0);
            decomp2(v.z * 0.125f, v.w * 0.125f, h1, l1);
            Kh[row * ATSTR + f4 * 2]     = h0;
            Kh[row * ATSTR + f4 * 2 + 1] = h1;
            Kl[row * ATSTR + f4 * 2]     = l0;
            Kl[row * ATSTR + f4 * 2 + 1] = l1;
        }
        __syncthreads();
        if ((wm >> 6) == p) {
            int r = (wm & 63) + gid;
            #pragma unroll
            for (int ks = 0; ks < 4; ks++) {
                qh[ks][0] = Kh[r * ATSTR + 8 * ks + tig];
                qh[ks][1] = Kh[(r + 8) * ATSTR + 8 * ks + tig];
                qh[ks][2] = Kh[r * ATSTR + 8 * ks + tig + 4];
                qh[ks][3] = Kh[(r + 8) * ATSTR + 8 * ks + tig + 4];
                ql[ks][0] = Kl[r * ATSTR + 8 * ks + tig];
                ql[ks][1] = Kl[(r + 8) * ATSTR + 8 * ks + tig];
                ql[ks][2] = Kl[r * ATSTR + 8 * ks + tig + 4];
                ql[ks][3] = Kl[(r + 8) * ATSTR + 8 * ks + tig + 4];
            }
        }
        __syncthreads();
    }

    float m0r = -1e30f, m1r = -1e30f, l0 = 0.f, l1 = 0.f;
    float o[8][4];
    #pragma unroll
    for (int nd = 0; nd < 8; nd++)
        #pragma unroll
        for (int e = 0; e < 4; e++) o[nd][e] = 0.f;

    const int nkt = 2 * qb + 2;
    for (int kt = 0; kt < nkt; kt++) {
        // ---- Load K tile: packed pairs over d, [j][dp] ----
        #pragma unroll
        for (int i = 0; i < 4; i++) {
            int lin = i * 256 + tid;
            int row = lin >> 4, f4 = lin & 15;
            float4 v = *(const float4*)(
                K + (size_t)(kt * 64 + row) * HS_ + f4 * 4);
            uint32_t h0, l0_, h1, l1_;
            decomp2(v.x, v.y, h0, l0_);
            decomp2(v.z, v.w, h1, l1_);
            Kh[row * ATSTR + f4 * 2]     = h0;
            Kh[row * ATSTR + f4 * 2 + 1] = h1;
            Kl[row * ATSTR + f4 * 2]     = l0_;
            Kl[row * ATSTR + f4 * 2 + 1] = l1_;
        }
        // ---- Load V tile transposed: packed pairs over t, [d][tp] ----
        #pragma unroll
        for (int i = 0; i < 2; i++) {
            int lin = i * 256 + tid;
            int tp = lin & 31, dg = lin >> 5;
            const float* v0p = V + (size_t)(kt * 64 + 2 * tp) * HS_ + dg * 4;
            float4 v0 = *(const float4*)v0p;
            float4 v1 = *(const float4*)(v0p + HS_);
            uint32_t hh, ll;
            decomp2(v0.x, v1.x, hh, ll);
            Vh[(dg * 4 + 0) * ATSTR + tp] = hh; Vl[(dg * 4 + 0) * ATSTR + tp] = ll;
            decomp2(v0.y, v1.y, hh, ll);
            Vh[(dg * 4 + 1) * ATSTR + tp] = hh; Vl[(dg * 4 + 1) * ATSTR + tp] = ll;
            decomp2(v0.z, v1.z, hh, ll);
            Vh[(dg * 4 + 2) * ATSTR + tp] = hh; Vl[(dg * 4 + 2) * ATSTR + tp] = ll;
            decomp2(v0.w, v1.w, hh, ll);
            Vh[(dg * 4 + 3) * ATSTR + tp] = hh; Vl[(dg * 4 + 3) * ATSTR + tp] = ll;
        }
        __syncthreads();

        // ---- S = Q K^T ----
        float s[8][4];
        #pragma unroll
        for (int nt = 0; nt < 8; nt++) {
            #pragma unroll
            for (int e = 0; e < 4; e++) s[nt][e] = 0.f;
            #pragma unroll
            for (int ks = 0; ks < 4; ks++) {
                int n = 8 * nt + gid;
                uint32_t bh[2], bl[2];
                bh[0] = Kh[n * ATSTR + 8 * ks + tig];
                bh[1] = Kh[n * ATSTR + 8 * ks + tig + 4];
                bl[0] = Kl[n * ATSTR + 8 * ks + tig];
                bl[1] = Kl[n * ATSTR + 8 * ks + tig + 4];
                mma_bf16(s[nt], qh[ks], bh);
                mma_bf16(s[nt], qh[ks], bl);
                mma_bf16(s[nt], ql[ks], bh);
            }
        }

        // ---- Causal mask (only tiles that can cross the diagonal) ----
        const int row0 = qb * 128 + wm + gid;
        if (64 * kt + 63 > qb * 128 + wm) {
            #pragma unroll
            for (int nt = 0; nt < 8; nt++) {
                int c0 = 64 * kt + 8 * nt + 2 * tig;
                if (c0 > row0)         s[nt][0] = -1e30f;
                if (c0 + 1 > row0)     s[nt][1] = -1e30f;
                if (c0 > row0 + 8)     s[nt][2] = -1e30f;
                if (c0 + 1 > row0 + 8) s[nt][3] = -1e30f;
            }
        }

        // ---- Online softmax (rows gid, gid+8; reduce over tig lanes) ----
        float rm0 = -1e30f, rm1 = -1e30f;
        #pragma unroll
        for (int nt = 0; nt < 8; nt++) {
            rm0 = fmaxf(rm0, fmaxf(s[nt][0], s[nt][1]));
            rm1 = fmaxf(rm1, fmaxf(s[nt][2], s[nt][3]));
        }
        #pragma unroll
        for (int off = 1; off < 4; off <<= 1) {
            rm0 = fmaxf(rm0, __shfl_xor_sync(0xffffffffu, rm0, off));
            rm1 = fmaxf(rm1, __shfl_xor_sync(0xffffffffu, rm1, off));
        }
        float mn0 = fmaxf(m0r, rm0), mn1 = fmaxf(m1r, rm1);
        float c0 = __expf(m0r - mn0), c1 = __expf(m1r - mn1);
        m0r = mn0; m1r = mn1;
        float rs0 = 0.f, rs1 = 0.f;
        #pragma unroll
        for (int nt = 0; nt < 8; nt++) {
            s[nt][0] = __expf(s[nt][0] - mn0);
            s[nt][1] = __expf(s[nt][1] - mn0);
            s[nt][2] = __expf(s[nt][2] - mn1);
            s[nt][3] = __expf(s[nt][3] - mn1);
            rs0 += s[nt][0] + s[nt][1];
            rs1 += s[nt][2] + s[nt][3];
        }
        #pragma unroll
        for (int off = 1; off < 4; off <<= 1) {
            rs0 += __shfl_xor_sync(0xffffffffu, rs0, off);
            rs1 += __shfl_xor_sync(0xffffffffu, rs1, off);
        }
        l0 = l0 * c0 + rs0;
        l1 = l1 * c1 + rs1;
        #pragma unroll
        for (int nd = 0; nd < 8; nd++) {
            o[nd][0] *= c0; o[nd][1] *= c0;
            o[nd][2] *= c1; o[nd][3] *= c1;
        }

        // ---- O += P V : P from score fragments (split hi/lo) ----
        #pragma unroll
        for (int ks = 0; ks < 4; ks++) {
            uint32_t ph[4], pl[4];
            {
                const float* sa = s[2 * ks];
                const float* sb = s[2 * ks + 1];
                decomp2(sa[0], sa[1], ph[0], pl[0]);
                decomp2(sa[2], sa[3], ph[1], pl[1]);
                decomp2(sb[0], sb[1], ph[2], pl[2]);
                decomp2(sb[2], sb[3], ph[3], pl[3]);
            }
            #pragma unroll
            for (int nd = 0; nd < 8; nd++) {
                int n = 8 * nd + gid;
                uint32_t bh[2], bl[2];
                bh[0] = Vh[n * ATSTR + 8 * ks + tig];
                bh[1] = Vh[n * ATSTR + 8 * ks + tig + 4];
                bl[0] = Vl[n * ATSTR + 8 * ks + tig];
                bl[1] = Vl[n * ATSTR + 8 * ks + tig + 4];
                mma_bf16(o[nd], ph, bh);
                mma_bf16(o[nd], ph, bl);
                mma_bf16(o[nd], pl, bh);
            }
        }
        __syncthreads();   // smem reads done before next tile overwrites
    }

    // ---- Epilogue: normalize and store ----
    float inv0 = 1.f / l0, inv1 = 1.f / l1;
    const int r0 = qb * 128 + wm + gid;
    #pragma unroll
    for (int nd = 0; nd < 8; nd++) {
        int d = 8 * nd + 2 * tig;
        *(float2*)(O + (size_t)r0 * HS_ + d) =
            make_float2(o[nd][0] * inv0, o[nd][1] * inv0);
        *(float2*)(O + (size_t)(r0 + 8) * HS_ + d) =
            make_float2(o[nd][2] * inv1, o[nd][3] * inv1);
    }
}

// ---------------------------------------------------------------------------
extern "C" void kernel_launch(void* const* d_in, const int* in_sizes, int n_in,
                              void* d_out, int out_size) {
    const float* x  = (const float*)d_in[0];
    const float* Wq = (const float*)d_in[1];
    const float* Wk = (const float*)d_in[2];
    const float* Wv = (const float*)d_in[3];
    const float* Wp = (const float*)d_in[4];
    const float* bp = (const float*)d_in[5];
    float* out = (float*)d_out;

    pack_w_kernel<<<(3 * C_ * KP_) / 256, 256>>>(Wq, Wk, Wv);
    pack_wp_kernel<<<(C_ * KP_) / 256, 256>>>(Wp);
    qkv_gemm<<<dim3(C_ / 128, M_ / 128, 3), 256>>>(x);
    attn_kernel<<<dim3(S_ / 128, H_, B_), 256>>>();
    proj_gemm<<<dim3(C_ / 128, M_ / 128), 256>>>(bp, out);
}

// round 6
// speedup vs baseline: 3.1803x; 1.0824x over previous
#include <cuda_runtime.h>
#include <cuda_bf16.h>
#include <cstdint>

constexpr int B_  = 4;
constexpr int S_  = 2048;
constexpr int C_  = 1024;
constexpr int H_  = 16;
constexpr int HS_ = 64;
constexpr int M_  = B_ * S_;                    // 8192
constexpr int QKV_ELEMS = B_ * H_ * S_ * HS_;   // 8388608
constexpr int KP_ = C_ / 2;                     // 512 packed k-pairs

__device__ float g_v[QKV_ELEMS];                    // V fp32 [B,H,S,HS] (pack_v input)
__device__ float g_o[QKV_ELEMS];                    // attention output [B,H,S,HS]
__device__ uint32_t g_whi[3 * C_ * KP_];            // [mat][n][kp] packed bf16 pairs
__device__ uint32_t g_wlo[3 * C_ * KP_];
__device__ uint32_t g_phi[C_ * KP_];                // [n][kp] for Wp^T
__device__ uint32_t g_plo[C_ * KP_];

// bf16 hi/lo planes for attention (packed pairs)
__device__ uint32_t q_hi[QKV_ELEMS / 2];            // [bh][s][dp]  (scaled 0.125)
__device__ uint32_t q_lo[QKV_ELEMS / 2];
__device__ uint32_t k_hi[QKV_ELEMS / 2];            // [bh][s][dp]
__device__ uint32_t k_lo[QKV_ELEMS / 2];
__device__ uint32_t v_hi[QKV_ELEMS / 2];            // [bh][d][tp]  (pairs over t)
__device__ uint32_t v_lo[QKV_ELEMS / 2];

// ---------------------------------------------------------------------------
__device__ __forceinline__ uint32_t pack2(__nv_bfloat16 a, __nv_bfloat16 b) {
    __nv_bfloat162 t; t.x = a; t.y = b;
    return *reinterpret_cast<uint32_t*>(&t);
}
__device__ __forceinline__ void decomp2(float a, float b, uint32_t& hi, uint32_t& lo) {
    __nv_bfloat16 ha = __float2bfloat16(a);
    __nv_bfloat16 hb = __float2bfloat16(b);
    __nv_bfloat16 la = __float2bfloat16(a - __bfloat162float(ha));
    __nv_bfloat16 lb = __float2bfloat16(b - __bfloat162float(hb));
    hi = pack2(ha, hb);
    lo = pack2(la, lb);
}

__device__ __forceinline__ void mma_bf16(float* d, const uint32_t* a, const uint32_t* b) {
    asm volatile(
        "mma.sync.aligned.m16n8k16.row.col.f32.bf16.bf16.f32 "
        "{%0,%1,%2,%3}, {%4,%5,%6,%7}, {%8,%9}, {%0,%1,%2,%3};\n"
        : "+f"(d[0]), "+f"(d[1]), "+f"(d[2]), "+f"(d[3])
        : "r"(a[0]), "r"(a[1]), "r"(a[2]), "r"(a[3]), "r"(b[0]), "r"(b[1]));
}

__device__ __forceinline__ void cp16(void* dst, const void* src) {
    uint32_t d = (uint32_t)__cvta_generic_to_shared(dst);
    asm volatile("cp.async.cg.shared.global [%0], [%1], 16;" :: "r"(d), "l"(src));
}
#define CP_COMMIT asm volatile("cp.async.commit_group;")
#define CP_WAIT0  asm volatile("cp.async.wait_group 0;")

// ---------------------------------------------------------------------------
// Weight packs (unchanged)
// ---------------------------------------------------------------------------
__global__ void pack_w_kernel(const float* __restrict__ Wq,
                              const float* __restrict__ Wk,
                              const float* __restrict__ Wv) {
    int idx = blockIdx.x * 256 + threadIdx.x;
    int mat = idx / (C_ * KP_);
    int rem = idx - mat * (C_ * KP_);
    int n   = rem >> 9;
    int kp  = rem & 511;
    const float* W = (mat == 0) ? Wq : (mat == 1) ? Wk : Wv;
    int h = n >> 6, d = n & 63;
    const float* base = W + (size_t)h * C_ * HS_ + (size_t)(2 * kp) * HS_ + d;
    uint32_t hi, lo;
    decomp2(base[0], base[HS_], hi, lo);
    g_whi[(size_t)mat * C_ * KP_ + (size_t)n * KP_ + kp] = hi;
    g_wlo[(size_t)mat * C_ * KP_ + (size_t)n * KP_ + kp] = lo;
}

__global__ void pack_wp_kernel(const float* __restrict__ Wp) {
    int idx = blockIdx.x * 256 + threadIdx.x;
    int n  = idx >> 9;
    int kp = idx & 511;
    float2 f = *(const float2*)(Wp + (size_t)n * C_ + 2 * kp);
    uint32_t hi, lo;
    decomp2(f.x, f.y, hi, lo);
    g_phi[(size_t)n * KP_ + kp] = hi;
    g_plo[(size_t)n * KP_ + kp] = lo;
}

// ---------------------------------------------------------------------------
// V transpose-pack: g_v [bh][t][d] fp32 -> v_hi/lo [bh][d][tp] bf16 pairs over t
// ---------------------------------------------------------------------------
__global__ __launch_bounds__(256) void pack_v_kernel() {
    const int bh = blockIdx.y;
    const int t0 = blockIdx.x * 128;
    __shared__ float sm[128][65];
    const int tid = threadIdx.x;

    const float* src = g_v + (size_t)bh * S_ * HS_ + (size_t)t0 * HS_;
    #pragma unroll
    for (int i = 0; i < 8; i++) {
        int lin = i * 256 + tid;          // 2048 float4
        int row = lin >> 4, c4 = lin & 15;
        float4 v = *(const float4*)(src + (size_t)row * HS_ + c4 * 4);
        sm[row][c4 * 4 + 0] = v.x;
        sm[row][c4 * 4 + 1] = v.y;
        sm[row][c4 * 4 + 2] = v.z;
        sm[row][c4 * 4 + 3] = v.w;
    }
    __syncthreads();

    const size_t obase = (size_t)bh * (HS_ * (S_ / 2)) + (size_t)(t0 >> 1);
    #pragma unroll
    for (int j = 0; j < 16; j++) {
        int d  = (tid >> 6) + j * 4;
        int tp = tid & 63;
        uint32_t hi, lo;
        decomp2(sm[2 * tp][d], sm[2 * tp + 1][d], hi, lo);
        v_hi[obase + (size_t)d * (S_ / 2) + tp] = hi;
        v_lo[obase + (size_t)d * (S_ / 2) + tp] = lo;
    }
}

// ---------------------------------------------------------------------------
// GEMM core (unchanged, proven)
// ---------------------------------------------------------------------------
constexpr int PSTR = 20;

__device__ __forceinline__ void gemm_compute(
    const uint32_t* Ah, const uint32_t* Al,
    const uint32_t* Bh, const uint32_t* Bl,
    int wm, int wn, int gid, int tig, float acc[4][4][4])
{
    #pragma unroll
    for (int ks = 0; ks < 2; ks++) {
        const int kb = ks * 8;
        uint32_t ah[4][4], al[4][4], bh[4][2], bl[4][2];
        #pragma unroll
        for (int mt = 0; mt < 4; mt++) {
            int r = wm + mt * 16 + gid;
            ah[mt][0] = Ah[r * PSTR + kb + tig];
            ah[mt][1] = Ah[(r + 8) * PSTR + kb + tig];
            ah[mt][2] = Ah[r * PSTR + kb + tig + 4];
            ah[mt][3] = Ah[(r + 8) * PSTR + kb + tig + 4];
            al[mt][0] = Al[r * PSTR + kb + tig];
            al[mt][1] = Al[(r + 8) * PSTR + kb + tig];
            al[mt][2] = Al[r * PSTR + kb + tig + 4];
            al[mt][3] = Al[(r + 8) * PSTR + kb + tig + 4];
        }
        #pragma unroll
        for (int nt = 0; nt < 4; nt++) {
            int n = wn + nt * 8 + gid;
            bh[nt][0] = Bh[n * PSTR + kb + tig];
            bh[nt][1] = Bh[n * PSTR + kb + tig + 4];
            bl[nt][0] = Bl[n * PSTR + kb + tig];
            bl[nt][1] = Bl[n * PSTR + kb + tig + 4];
        }
        #pragma unroll
        for (int mt = 0; mt < 4; mt++)
            #pragma unroll
            for (int nt = 0; nt < 4; nt++) {
                mma_bf16(acc[mt][nt], ah[mt], bh[nt]);
                mma_bf16(acc[mt][nt], ah[mt], bl[nt]);
                mma_bf16(acc[mt][nt], al[mt], bh[nt]);
            }
    }
}

// ---------------------------------------------------------------------------
// QKV GEMM. Epilogue: Q/K write packed hi/lo planes (Q scaled); V writes fp32.
// ---------------------------------------------------------------------------
__global__ __launch_bounds__(256, 2) void qkv_gemm(const float* __restrict__ x) {
    const int mat = blockIdx.z;
    const uint32_t* Whi = g_whi + (size_t)mat * C_ * KP_;
    const uint32_t* Wlo = g_wlo + (size_t)mat * C_ * KP_;

    const int n0 = blockIdx.x * 128;
    const int m0 = blockIdx.y * 128;

    __shared__ uint32_t Ah[128 * PSTR], Al[128 * PSTR];
    __shared__ uint32_t Bh[128 * PSTR], Bl[128 * PSTR];

    const int tid  = threadIdx.x;
    const int warp = tid >> 5;
    const int lane = tid & 31;
    const int gid  = lane >> 2;
    const int tig  = lane & 3;
    const int wm   = (warp & 1) * 64;
    const int wn   = (warp >> 1) * 32;

    float acc[4][4][4];
    #pragma unroll
    for (int mt = 0; mt < 4; mt++)
        #pragma unroll
        for (int nt = 0; nt < 4; nt++)
            #pragma unroll
            for (int e = 0; e < 4; e++) acc[mt][nt][e] = 0.f;

    for (int k0 = 0; k0 < C_; k0 += 32) {
        const int kp0 = k0 >> 1;
        #pragma unroll
        for (int i = 0; i < 4; i++) {
            int lin = i * 256 + tid;
            int row = lin >> 3, c4 = lin & 7;
            float4 v = *(const float4*)(x + (size_t)(m0 + row) * C_ + k0 + c4 * 4);
            uint32_t h0, l0, h1, l1;
            decomp2(v.x, v.y, h0, l0);
            decomp2(v.z, v.w, h1, l1);
            Ah[row * PSTR + c4 * 2]     = h0;
            Ah[row * PSTR + c4 * 2 + 1] = h1;
            Al[row * PSTR + c4 * 2]     = l0;
            Al[row * PSTR + c4 * 2 + 1] = l1;
        }
        #pragma unroll
        for (int i = 0; i < 2; i++) {
            int lin = i * 256 + tid;
            int n = lin >> 2, kq = lin & 3;
            uint4 vh = *(const uint4*)(Whi + (size_t)(n0 + n) * KP_ + kp0 + kq * 4);
            uint4 vl = *(const uint4*)(Wlo + (size_t)(n0 + n) * KP_ + kp0 + kq * 4);
            Bh[n * PSTR + kq * 4 + 0] = vh.x;
            Bh[n * PSTR + kq * 4 + 1] = vh.y;
            Bh[n * PSTR + kq * 4 + 2] = vh.z;
            Bh[n * PSTR + kq * 4 + 3] = vh.w;
            Bl[n * PSTR + kq * 4 + 0] = vl.x;
            Bl[n * PSTR + kq * 4 + 1] = vl.y;
            Bl[n * PSTR + kq * 4 + 2] = vl.z;
            Bl[n * PSTR + kq * 4 + 3] = vl.w;
        }
        __syncthreads();
        gemm_compute(Ah, Al, Bh, Bl, wm, wn, gid, tig, acc);
        __syncthreads();
    }

    if (mat == 2) {
        // V: fp32 [b,h,s,d]
        #pragma unroll
        for (int mt = 0; mt < 4; mt++) {
            int r  = m0 + wm + mt * 16 + gid;
            int b  = r >> 11;
            int s0 = r & 2047;
            #pragma unroll
            for (int nt = 0; nt < 4; nt++) {
                int n    = n0 + wn + nt * 8 + 2 * tig;
                int head = n >> 6;
                int d    = n & 63;
                float* p0 = g_v + ((size_t)(b * H_ + head) * S_ + s0) * HS_ + d;
                *(float2*)p0             = make_float2(acc[mt][nt][0], acc[mt][nt][1]);
                *(float2*)(p0 + 8 * HS_) = make_float2(acc[mt][nt][2], acc[mt][nt][3]);
            }
        }
    } else {
        const float scale = (mat == 0) ? 0.125f : 1.0f;
        uint32_t* hiP = (mat == 0) ? q_hi : k_hi;
        uint32_t* loP = (mat == 0) ? q_lo : k_lo;
        #pragma unroll
        for (int mt = 0; mt < 4; mt++) {
            int r  = m0 + wm + mt * 16 + gid;
            int b  = r >> 11;
            int s0 = r & 2047;
            #pragma unroll
            for (int nt = 0; nt < 4; nt++) {
                int n    = n0 + wn + nt * 8 + 2 * tig;
                int head = n >> 6;
                int dp   = (n & 63) >> 1;
                size_t i0 = ((size_t)(b * H_ + head) * S_ + s0) * 32 + dp;
                uint32_t hi, lo;
                decomp2(acc[mt][nt][0] * scale, acc[mt][nt][1] * scale, hi, lo);
                hiP[i0] = hi; loP[i0] = lo;
                decomp2(acc[mt][nt][2] * scale, acc[mt][nt][3] * scale, hi, lo);
                hiP[i0 + 8 * 32] = hi; loP[i0 + 8 * 32] = lo;
            }
        }
    }
}

// ---------------------------------------------------------------------------
// Projection GEMM (unchanged)
// ---------------------------------------------------------------------------
__global__ __launch_bounds__(256, 2) void proj_gemm(
    const float* __restrict__ bp, float* __restrict__ out)
{
    const int n0 = blockIdx.x * 128;
    const int m0 = blockIdx.y * 128;

    __shared__ uint32_t Ah[128 * PSTR], Al[128 * PSTR];
    __shared__ uint32_t Bh[128 * PSTR], Bl[128 * PSTR];

    const int tid  = threadIdx.x;
    const int warp = tid >> 5;
    const int lane = tid & 31;
    const int gid  = lane >> 2;
    const int tig  = lane & 3;
    const int wm   = (warp & 1) * 64;
    const int wn   = (warp >> 1) * 32;

    float acc[4][4][4];
    #pragma unroll
    for (int mt = 0; mt < 4; mt++)
        #pragma unroll
        for (int nt = 0; nt < 4; nt++)
            #pragma unroll
            for (int e = 0; e < 4; e++) acc[mt][nt][e] = 0.f;

    for (int k0 = 0; k0 < C_; k0 += 32) {
        const int kp0 = k0 >> 1;
        #pragma unroll
        for (int i = 0; i < 4; i++) {
            int lin = i * 256 + tid;
            int row = lin >> 3, c4 = lin & 7;
            int m   = m0 + row;
            int bb  = m >> 11;
            int ss  = m & 2047;
            int kg  = k0 + c4 * 4;
            float4 v = *(const float4*)(
                g_o + ((size_t)(bb * H_ + (kg >> 6)) * S_ + ss) * HS_ + (kg & 63));
            uint32_t h0, l0, h1, l1;
            decomp2(v.x, v.y, h0, l0);
            decomp2(v.z, v.w, h1, l1);
            Ah[row * PSTR + c4 * 2]     = h0;
            Ah[row * PSTR + c4 * 2 + 1] = h1;
            Al[row * PSTR + c4 * 2]     = l0;
            Al[row * PSTR + c4 * 2 + 1] = l1;
        }
        #pragma unroll
        for (int i = 0; i < 2; i++) {
            int lin = i * 256 + tid;
            int n = lin >> 2, kq = lin & 3;
            uint4 vh = *(const uint4*)(g_phi + (size_t)(n0 + n) * KP_ + kp0 + kq * 4);
            uint4 vl = *(const uint4*)(g_plo + (size_t)(n0 + n) * KP_ + kp0 + kq * 4);
            Bh[n * PSTR + kq * 4 + 0] = vh.x;
            Bh[n * PSTR + kq * 4 + 1] = vh.y;
            Bh[n * PSTR + kq * 4 + 2] = vh.z;
            Bh[n * PSTR + kq * 4 + 3] = vh.w;
            Bl[n * PSTR + kq * 4 + 0] = vl.x;
            Bl[n * PSTR + kq * 4 + 1] = vl.y;
            Bl[n * PSTR + kq * 4 + 2] = vl.z;
            Bl[n * PSTR + kq * 4 + 3] = vl.w;
        }
        __syncthreads();
        gemm_compute(Ah, Al, Bh, Bl, wm, wn, gid, tig, acc);
        __syncthreads();
    }

    #pragma unroll
    for (int mt = 0; mt < 4; mt++) {
        int r = m0 + wm + mt * 16 + gid;
        #pragma unroll
        for (int nt = 0; nt < 4; nt++) {
            int n = n0 + wn + nt * 8 + 2 * tig;
            float2 bias = *(const float2*)(bp + n);
            *(float2*)(out + (size_t)r * C_ + n) =
                make_float2(acc[mt][nt][0] + bias.x, acc[mt][nt][1] + bias.y);
            *(float2*)(out + (size_t)(r + 8) * C_ + n) =
                make_float2(acc[mt][nt][2] + bias.x, acc[mt][nt][3] + bias.y);
        }
    }
}

// ---------------------------------------------------------------------------
// Flash attention, tensor cores + cp.async pipeline.
// Pre-split bf16 planes in gmem; K(kt+1) load overlaps PV(kt), V(kt) overlaps S(kt).
// ---------------------------------------------------------------------------
constexpr int AST = 36;

__global__ __launch_bounds__(256, 2) void attn_kernel() {
    const int qb = (int)gridDim.x - 1 - (int)blockIdx.x;   // big tiles first
    const int bh = blockIdx.z * H_ + blockIdx.y;

    const uint32_t* Qhg = q_hi + (size_t)bh * S_ * 32;
    const uint32_t* Qlg = q_lo + (size_t)bh * S_ * 32;
    const uint32_t* Khg = k_hi + (size_t)bh * S_ * 32;
    const uint32_t* Klg = k_lo + (size_t)bh * S_ * 32;
    const uint32_t* Vhg = v_hi + (size_t)bh * (HS_ * (S_ / 2));
    const uint32_t* Vlg = v_lo + (size_t)bh * (HS_ * (S_ / 2));
    float* O = g_o + (size_t)bh * S_ * HS_;

    const int tid  = threadIdx.x;
    const int warp = tid >> 5;
    const int lane = tid & 31;
    const int gid  = lane >> 2;
    const int tig  = lane & 3;
    const int wm   = warp * 16;

    __shared__ uint32_t Kh[64 * AST], Kl[64 * AST];
    __shared__ uint32_t Vh[64 * AST], Vl[64 * AST];

    // Q fragments straight from gmem planes
    const int rg = qb * 128 + wm + gid;
    uint32_t qh[4][4], ql[4][4];
    #pragma unroll
    for (int ks = 0; ks < 4; ks++) {
        int off = 8 * ks + tig;
        qh[ks][0] = Qhg[(size_t)rg * 32 + off];
        qh[ks][1] = Qhg[(size_t)(rg + 8) * 32 + off];
        qh[ks][2] = Qhg[(size_t)rg * 32 + off + 4];
        qh[ks][3] = Qhg[(size_t)(rg + 8) * 32 + off + 4];
        ql[ks][0] = Qlg[(size_t)rg * 32 + off];
        ql[ks][1] = Qlg[(size_t)(rg + 8) * 32 + off];
        ql[ks][2] = Qlg[(size_t)rg * 32 + off + 4];
        ql[ks][3] = Qlg[(size_t)(rg + 8) * 32 + off + 4];
    }

    float m0r = -1e30f, m1r = -1e30f, l0 = 0.f, l1 = 0.f;
    float o[8][4];
    #pragma unroll
    for (int nd = 0; nd < 8; nd++)
        #pragma unroll
        for (int e = 0; e < 4; e++) o[nd][e] = 0.f;

    const int nkt = 2 * qb + 2;

    // issue K tile kt (1024 16B chunks over 256 threads)
    auto issueK = [&](int kt) {
        #pragma unroll
        for (int i = 0; i < 4; i++) {
            int c   = i * 256 + tid;
            int pl  = c >> 9;
            int row = (c >> 3) & 63;
            int ch  = c & 7;
            uint32_t* sdst = (pl ? Kl : Kh) + row * AST + ch * 4;
            const uint32_t* gsrc = (pl ? Klg : Khg) + (size_t)(kt * 64 + row) * 32 + ch * 4;
            cp16(sdst, gsrc);
        }
        CP_COMMIT;
    };
    auto issueV = [&](int kt) {
        #pragma unroll
        for (int i = 0; i < 4; i++) {
            int c   = i * 256 + tid;
            int pl  = c >> 9;
            int row = (c >> 3) & 63;    // d
            int ch  = c & 7;
            uint32_t* sdst = (pl ? Vl : Vh) + row * AST + ch * 4;
            const uint32_t* gsrc = (pl ? Vlg : Vhg) + (size_t)row * (S_ / 2) + kt * 32 + ch * 4;
            cp16(sdst, gsrc);
        }
        CP_COMMIT;
    };

    issueK(0);

    for (int kt = 0; kt < nkt; kt++) {
        CP_WAIT0;             // K(kt) landed (and prior PV fully read V per loop-end sync)
        __syncthreads();
        issueV(kt);           // overlaps S compute

        const bool active = (64 * kt) <= (rg + 8);   // any unmasked col for this warp?
        float s[8][4];
        if (active) {
            #pragma unroll
            for (int nt = 0; nt < 8; nt++) {
                #pragma unroll
                for (int e = 0; e < 4; e++) s[nt][e] = 0.f;
                #pragma unroll
                for (int ks = 0; ks < 4; ks++) {
                    int n = 8 * nt + gid;
                    uint32_t bh2[2], bl2[2];
                    bh2[0] = Kh[n * AST + 8 * ks + tig];
                    bh2[1] = Kh[n * AST + 8 * ks + tig + 4];
                    bl2[0] = Kl[n * AST + 8 * ks + tig];
                    bl2[1] = Kl[n * AST + 8 * ks + tig + 4];
                    mma_bf16(s[nt], qh[ks], bh2);
                    mma_bf16(s[nt], qh[ks], bl2);
                    mma_bf16(s[nt], ql[ks], bh2);
                }
            }
            // causal mask
            if (64 * kt + 63 > rg) {
                #pragma unroll
                for (int nt = 0; nt < 8; nt++) {
                    int c0 = 64 * kt + 8 * nt + 2 * tig;
                    if (c0 > rg)         s[nt][0] = -1e30f;
                    if (c0 + 1 > rg)     s[nt][1] = -1e30f;
                    if (c0 > rg + 8)     s[nt][2] = -1e30f;
                    if (c0 + 1 > rg + 8) s[nt][3] = -1e30f;
                }
            }
            // online softmax
            float rm0 = -1e30f, rm1 = -1e30f;
            #pragma unroll
            for (int nt = 0; nt < 8; nt++) {
                rm0 = fmaxf(rm0, fmaxf(s[nt][0], s[nt][1]));
                rm1 = fmaxf(rm1, fmaxf(s[nt][2], s[nt][3]));
            }
            #pragma unroll
            for (int off = 1; off < 4; off <<= 1) {
                rm0 = fmaxf(rm0, __shfl_xor_sync(0xffffffffu, rm0, off));
                rm1 = fmaxf(rm1, __shfl_xor_sync(0xffffffffu, rm1, off));
            }
            float mn0 = fmaxf(m0r, rm0), mn1 = fmaxf(m1r, rm1);
            float c0 = __expf(m0r - mn0), c1 = __expf(m1r - mn1);
            m0r = mn0; m1r = mn1;
            float rs0 = 0.f, rs1 = 0.f;
            #pragma unroll
            for (int nt = 0; nt < 8; nt++) {
                s[nt][0] = __expf(s[nt][0] - mn0);
                s[nt][1] = __expf(s[nt][1] - mn0);
                s[nt][2] = __expf(s[nt][2] - mn1);
                s[nt][3] = __expf(s[nt][3] - mn1);
                rs0 += s[nt][0] + s[nt][1];
                rs1 += s[nt][2] + s[nt][3];
            }
            #pragma unroll
            for (int off = 1; off < 4; off <<= 1) {
                rs0 += __shfl_xor_sync(0xffffffffu, rs0, off);
                rs1 += __shfl_xor_sync(0xffffffffu, rs1, off);
            }
            l0 = l0 * c0 + rs0;
            l1 = l1 * c1 + rs1;
            #pragma unroll
            for (int nd = 0; nd < 8; nd++) {
                o[nd][0] *= c0; o[nd][1] *= c0;
                o[nd][2] *= c1; o[nd][3] *= c1;
            }
        }

        CP_WAIT0;             // V(kt) landed
        __syncthreads();      // all warps done reading K(kt)
        if (kt + 1 < nkt) issueK(kt + 1);   // overlaps PV compute

        if (active) {
            #pragma unroll
            for (int ks = 0; ks < 4; ks++) {
                uint32_t ph[4], pl2[4];
                {
                    const float* sa = s[2 * ks];
                    const float* sb = s[2 * ks + 1];
                    decomp2(sa[0], sa[1], ph[0], pl2[0]);
                    decomp2(sa[2], sa[3], ph[1], pl2[1]);
                    decomp2(sb[0], sb[1], ph[2], pl2[2]);
                    decomp2(sb[2], sb[3], ph[3], pl2[3]);
                }
                #pragma unroll
                for (int nd = 0; nd < 8; nd++) {
                    int n = 8 * nd + gid;
                    uint32_t bh2[2], bl2[2];
                    bh2[0] = Vh[n * AST + 8 * ks + tig];
                    bh2[1] = Vh[n * AST + 8 * ks + tig + 4];
                    bl2[0] = Vl[n * AST + 8 * ks + tig];
                    bl2[1] = Vl[n * AST + 8 * ks + tig + 4];
                    mma_bf16(o[nd], ph, bh2);
                    mma_bf16(o[nd], ph, bl2);
                    mma_bf16(o[nd], pl2, bh2);
                }
            }
        }
        __syncthreads();      // all warps done reading V(kt) before next issueV
    }

    float inv0 = 1.f / l0, inv1 = 1.f / l1;
    #pragma unroll
    for (int nd = 0; nd < 8; nd++) {
        int d = 8 * nd + 2 * tig;
        *(float2*)(O + (size_t)rg * HS_ + d) =
            make_float2(o[nd][0] * inv0, o[nd][1] * inv0);
        *(float2*)(O + (size_t)(rg + 8) * HS_ + d) =
            make_float2(o[nd][2] * inv1, o[nd][3] * inv1);
    }
}

// ---------------------------------------------------------------------------
extern "C" void kernel_launch(void* const* d_in, const int* in_sizes, int n_in,
                              void* d_out, int out_size) {
    const float* x  = (const float*)d_in[0];
    const float* Wq = (const float*)d_in[1];
    const float* Wk = (const float*)d_in[2];
    const float* Wv = (const float*)d_in[3];
    const float* Wp = (const float*)d_in[4];
    const float* bp = (const float*)d_in[5];
    float* out = (float*)d_out;

    pack_w_kernel<<<(3 * C_ * KP_) / 256, 256>>>(Wq, Wk, Wv);
    pack_wp_kernel<<<(C_ * KP_) / 256, 256>>>(Wp);
    qkv_gemm<<<dim3(C_ / 128, M_ / 128, 3), 256>>>(x);
    pack_v_kernel<<<dim3(S_ / 128, B_ * H_), 256>>>();
    attn_kernel<<<dim3(S_ / 128, H_, B_), 256>>>();
    proj_gemm<<<dim3(C_ / 128, M_ / 128), 256>>>(bp, out);
}